// round 8
// baseline (speedup 1.0000x reference)
#include <cuda_runtime.h>
#include <cuda_bf16.h>
#include <cstdint>

// Problem constants
#define BATCH 2
#define SEQ   2048
#define EMB   1024
#define HEADS 16
#define HDIM  64
#define C3    (3 * EMB)
#define MTOT  (BATCH * SEQ)   // 4096

// Scratch (allocation-free rule: __device__ globals)
__device__ __nv_bfloat16 g_x_h[MTOT * EMB];
__device__ __nv_bfloat16 g_x_l[MTOT * EMB];
__device__ __nv_bfloat16 g_wa_h[C3 * EMB];
__device__ __nv_bfloat16 g_wa_l[C3 * EMB];
__device__ __nv_bfloat16 g_wp_h[EMB * EMB];
__device__ __nv_bfloat16 g_wp_l[EMB * EMB];
__device__ __nv_bfloat16 g_qkv_h[MTOT * C3];
__device__ __nv_bfloat16 g_qkv_l[MTOT * C3];
__device__ __nv_bfloat16 g_y_h[MTOT * EMB];
__device__ __nv_bfloat16 g_y_l[MTOT * EMB];

// ---------------------------------------------------------------------------
// helpers (plain sm_80-level PTX: valid at compute_103)
// ---------------------------------------------------------------------------
__device__ __forceinline__ uint32_t smem_u32(const void* p) {
    uint32_t a;
    asm("{ .reg .u64 t; cvta.to.shared.u64 t, %1; cvt.u32.u64 %0, t; }"
        : "=r"(a) : "l"(p));
    return a;
}

__device__ __forceinline__ void cpasync16(uint32_t dst, const void* src) {
    asm volatile("cp.async.cg.shared.global [%0], [%1], 16;"
                 :: "r"(dst), "l"(src) : "memory");
}
#define CP_COMMIT() asm volatile("cp.async.commit_group;" ::: "memory")

__device__ __forceinline__ void ldsm4(uint32_t* r, uint32_t addr) {
    asm volatile("ldmatrix.sync.aligned.m8n8.x4.shared.b16 {%0,%1,%2,%3}, [%4];"
                 : "=r"(r[0]), "=r"(r[1]), "=r"(r[2]), "=r"(r[3]) : "r"(addr));
}
__device__ __forceinline__ void ldsm4t(uint32_t* r, uint32_t addr) {
    asm volatile("ldmatrix.sync.aligned.m8n8.x4.trans.shared.b16 {%0,%1,%2,%3}, [%4];"
                 : "=r"(r[0]), "=r"(r[1]), "=r"(r[2]), "=r"(r[3]) : "r"(addr));
}

__device__ __forceinline__ void mma16816(float* c, const uint32_t* a,
                                         uint32_t b0, uint32_t b1) {
    asm volatile(
        "mma.sync.aligned.m16n8k16.row.col.f32.bf16.bf16.f32 "
        "{%0,%1,%2,%3}, {%4,%5,%6,%7}, {%8,%9}, {%0,%1,%2,%3};"
        : "+f"(c[0]), "+f"(c[1]), "+f"(c[2]), "+f"(c[3])
        : "r"(a[0]), "r"(a[1]), "r"(a[2]), "r"(a[3]), "r"(b0), "r"(b1));
}

#define SWZ(o) ((o) ^ (((o) >> 3) & 0x70))

__device__ __forceinline__ uint32_t pack_split(float x, float y, uint32_t& lo) {
    __nv_bfloat162 h = __floats2bfloat162_rn(x, y);
    const float2 f = __bfloat1622float2(h);
    __nv_bfloat162 l = __floats2bfloat162_rn(x - f.x, y - f.y);
    lo = *(uint32_t*)&l;
    return *(uint32_t*)&h;
}

// ---------------------------------------------------------------------------
// split fp32 -> (hi, lo) bf16
// ---------------------------------------------------------------------------
__global__ __launch_bounds__(256) void split_kernel(
    const float4* __restrict__ in, uint2* __restrict__ hi,
    uint2* __restrict__ lo, int n4)
{
    const int i = blockIdx.x * 256 + threadIdx.x;
    if (i >= n4) return;
    const float4 v = in[i];
    __nv_bfloat162 h0 = __floats2bfloat162_rn(v.x, v.y);
    __nv_bfloat162 h1 = __floats2bfloat162_rn(v.z, v.w);
    const float2 f0 = __bfloat1622float2(h0);
    const float2 f1 = __bfloat1622float2(h1);
    __nv_bfloat162 l0 = __floats2bfloat162_rn(v.x - f0.x, v.y - f0.y);
    __nv_bfloat162 l1 = __floats2bfloat162_rn(v.z - f1.x, v.w - f1.y);
    hi[i] = make_uint2(*(uint32_t*)&h0, *(uint32_t*)&h1);
    lo[i] = make_uint2(*(uint32_t*)&l0, *(uint32_t*)&l1);
}

// ---------------------------------------------------------------------------
// HMMA NT GEMM: C = A @ B^T + bias (A,B pre-split bf16). 3-pass split accum.
// 512 threads, 16 warps in a 4x4 grid, warp tile 32x32 (occ: 4 warps/SMSP).
// CTA tile 128x128, BK=64, cp.async double-buffered.
// ---------------------------------------------------------------------------
#define TILE_B  16384
#define STAGE_B (4 * TILE_B)
#define GSMEM   (2 * STAGE_B + 1024)

template<bool SPLIT_OUT>
__global__ __launch_bounds__(512, 1) void gemm_hmma(
    const __nv_bfloat16* __restrict__ Ah, const __nv_bfloat16* __restrict__ Al,
    const __nv_bfloat16* __restrict__ Bh, const __nv_bfloat16* __restrict__ Bl,
    const float* __restrict__ bias, float* __restrict__ C,
    __nv_bfloat16* __restrict__ Ch, __nv_bfloat16* __restrict__ Cl,
    int M, int N, int K)
{
    extern __shared__ char smr[];
    const uint32_t sb = (smem_u32(smr) + 1023u) & ~1023u;

    const int t    = threadIdx.x;
    const int lane = t & 31;
    const int wid  = t >> 5;
    const int warp_m = wid & 3;     // 0..3 (32 rows each)
    const int warp_n = wid >> 2;    // 0..3 (32 cols each)
    const int bm = blockIdx.y * 128;
    const int bn = blockIdx.x * 128;

    const int lg = lane >> 3, lr = lane & 7;
    const int a_mloc = (lg & 1) * 8 + lr;  const int a_kh = lg >> 1;
    const int b_nloc = (lg >> 1) * 8 + lr; const int b_kh = lg & 1;

    const int NC = K >> 6;

    auto issue = [&](int kt, int stage) {
        const uint32_t base = sb + stage * STAGE_B;
        const int k0 = kt << 6;
#pragma unroll
        for (int l = 0; l < 2; l++) {
            const int idx = t + 512 * l;
            const int row = idx >> 3;
            const int ch  = idx & 7;
            const uint32_t sw = SWZ((uint32_t)(row * 128 + ch * 16));
            const size_t ga = (size_t)(bm + row) * K + k0 + ch * 8;
            const size_t gb = (size_t)(bn + row) * K + k0 + ch * 8;
            cpasync16(base + sw,              Ah + ga);
            cpasync16(base + TILE_B + sw,     Al + ga);
            cpasync16(base + 2 * TILE_B + sw, Bh + gb);
            cpasync16(base + 3 * TILE_B + sw, Bl + gb);
        }
    };

    float acc[2][4][4];
#pragma unroll
    for (int i = 0; i < 2; i++)
#pragma unroll
        for (int j = 0; j < 4; j++)
#pragma unroll
            for (int e = 0; e < 4; e++) acc[i][j][e] = 0.0f;

    issue(0, 0);
    CP_COMMIT();

    for (int kt = 0; kt < NC; kt++) {
        if (kt + 1 < NC) {
            issue(kt + 1, (kt + 1) & 1);
            CP_COMMIT();
            asm volatile("cp.async.wait_group 1;" ::: "memory");
        } else {
            asm volatile("cp.async.wait_group 0;" ::: "memory");
        }
        __syncthreads();

        const uint32_t base = sb + (kt & 1) * STAGE_B;
#pragma unroll
        for (int ks = 0; ks < 4; ks++) {
            uint32_t ah[2][4], al[2][4], bh[2][4], bl[2][4];
#pragma unroll
            for (int mt = 0; mt < 2; mt++) {
                const int row = warp_m * 32 + mt * 16 + a_mloc;
                const uint32_t sw = SWZ((uint32_t)(row * 128 + ks * 32 + a_kh * 16));
                ldsm4(ah[mt], base + sw);
                ldsm4(al[mt], base + TILE_B + sw);
            }
#pragma unroll
            for (int np = 0; np < 2; np++) {
                const int row = warp_n * 32 + np * 16 + b_nloc;
                const uint32_t sw = SWZ((uint32_t)(row * 128 + ks * 32 + b_kh * 16));
                ldsm4(bh[np], base + 2 * TILE_B + sw);
                ldsm4(bl[np], base + 3 * TILE_B + sw);
            }
#pragma unroll
            for (int mt = 0; mt < 2; mt++)
#pragma unroll
                for (int nt = 0; nt < 4; nt++)
                    mma16816(acc[mt][nt], ah[mt],
                             bh[nt >> 1][(nt & 1) * 2], bh[nt >> 1][(nt & 1) * 2 + 1]);
#pragma unroll
            for (int mt = 0; mt < 2; mt++)
#pragma unroll
                for (int nt = 0; nt < 4; nt++)
                    mma16816(acc[mt][nt], ah[mt],
                             bl[nt >> 1][(nt & 1) * 2], bl[nt >> 1][(nt & 1) * 2 + 1]);
#pragma unroll
            for (int mt = 0; mt < 2; mt++)
#pragma unroll
                for (int nt = 0; nt < 4; nt++)
                    mma16816(acc[mt][nt], al[mt],
                             bh[nt >> 1][(nt & 1) * 2], bh[nt >> 1][(nt & 1) * 2 + 1]);
        }
        __syncthreads();
    }

#pragma unroll
    for (int mt = 0; mt < 2; mt++) {
        const int row = bm + warp_m * 32 + mt * 16 + (lane >> 2);
#pragma unroll
        for (int nt = 0; nt < 4; nt++) {
            const int col = bn + warp_n * 32 + nt * 8 + (lane & 3) * 2;
            const float2 bb = *(const float2*)(bias + col);
            const float c00 = acc[mt][nt][0] + bb.x;
            const float c01 = acc[mt][nt][1] + bb.y;
            const float c10 = acc[mt][nt][2] + bb.x;
            const float c11 = acc[mt][nt][3] + bb.y;
            if (SPLIT_OUT) {
                uint32_t lo0, lo1;
                const uint32_t hi0 = pack_split(c00, c01, lo0);
                const uint32_t hi1 = pack_split(c10, c11, lo1);
                *(uint32_t*)(Ch + (size_t)row * N + col)       = hi0;
                *(uint32_t*)(Cl + (size_t)row * N + col)       = lo0;
                *(uint32_t*)(Ch + (size_t)(row + 8) * N + col) = hi1;
                *(uint32_t*)(Cl + (size_t)(row + 8) * N + col) = lo1;
            } else {
                *(float2*)(C + (size_t)row * N + col)       = make_float2(c00, c01);
                *(float2*)(C + (size_t)(row + 8) * N + col) = make_float2(c10, c11);
            }
        }
    }
}

// ---------------------------------------------------------------------------
// HMMA flash attention. CTA: 64 q-rows x (head, batch), 128 threads (4 warps
// x 16 rows). Grid 32x16x2 = 1024 CTAs; ~81KB smem -> 2 CTAs/SM.
// k-blocks of 64 double-buffered; inner structure identical to round 7.
// ---------------------------------------------------------------------------
#define KTILE_B   8192           // 64 rows * 128 B
#define ASTAGE_B  (4 * KTILE_B)  // 32 KB
#define ASMEM     (16384 + 2 * ASTAGE_B + 1024)

__global__ __launch_bounds__(128, 2) void attn_hmma(
    const __nv_bfloat16* __restrict__ Gh, const __nv_bfloat16* __restrict__ Gl,
    __nv_bfloat16* __restrict__ Yh, __nv_bfloat16* __restrict__ Yl)
{
    extern __shared__ char smr[];
    const uint32_t sb  = (smem_u32(smr) + 1023u) & ~1023u;
    const uint32_t sQh = sb;
    const uint32_t sQl = sb + 8192;
    const uint32_t sKV = sb + 16384;

    const int t = threadIdx.x;
    const int lane = t & 31, wid = t >> 5;
    const int lg = lane >> 3, lr = lane & 7;
    const int a_mloc = (lg & 1) * 8 + lr, a_kh = lg >> 1;
    const int b_nloc = (lg >> 1) * 8 + lr, b_kh = lg & 1;

    const int qt = gridDim.x - 1 - blockIdx.x;   // heaviest first
    const int h  = blockIdx.y;
    const int b  = blockIdx.z;

    const size_t qrow0 = (size_t)b * SEQ + qt * 64;
    const size_t hoff  = (size_t)h * HDIM;

    // prologue: Q tiles (64 rows)
#pragma unroll
    for (int l = 0; l < 4; l++) {
        const int idx = t + 128 * l;
        const int row = idx >> 3, ch = idx & 7;
        const uint32_t sw = SWZ((uint32_t)(row * 128 + ch * 16));
        const size_t g = (qrow0 + row) * C3 + hoff + ch * 8;
        cpasync16(sQh + sw, Gh + g);
        cpasync16(sQl + sw, Gl + g);
    }
    CP_COMMIT();

    auto fill = [&](int kb, int st) {
        const uint32_t base = sKV + st * ASTAGE_B;
#pragma unroll
        for (int l = 0; l < 4; l++) {
            const int idx = t + 128 * l;
            const int row = idx >> 3, ch = idx & 7;
            const uint32_t sw = SWZ((uint32_t)(row * 128 + ch * 16));
            const size_t g = ((size_t)b * SEQ + kb * 64 + row) * C3 + hoff + ch * 8;
            cpasync16(base + sw,               Gh + g + EMB);       // Kh
            cpasync16(base + KTILE_B + sw,     Gl + g + EMB);       // Kl
            cpasync16(base + 2 * KTILE_B + sw, Gh + g + 2 * EMB);   // Vh
            cpasync16(base + 3 * KTILE_B + sw, Gl + g + 2 * EMB);   // Vl
        }
    };
    fill(0, 0);
    CP_COMMIT();
    asm volatile("cp.async.wait_group 0;" ::: "memory");
    __syncthreads();

    // Q fragments (registers, whole CTA lifetime)
    uint32_t qh[4][4], ql[4][4];
#pragma unroll
    for (int ks = 0; ks < 4; ks++) {
        const int row = wid * 16 + a_mloc;
        const uint32_t sw = SWZ((uint32_t)(row * 128 + ks * 32 + a_kh * 16));
        ldsm4(qh[ks], sQh + sw);
        ldsm4(ql[ks], sQl + sw);
    }

    float of[8][4];
#pragma unroll
    for (int i = 0; i < 8; i++)
#pragma unroll
        for (int e = 0; e < 4; e++) of[i][e] = 0.0f;
    float m_run[2] = {-1e30f, -1e30f};
    float l_run[2] = {0.0f, 0.0f};

    const int nkb = qt + 1;
    for (int kb = 0; kb < nkb; kb++) {
        if (kb + 1 < nkb) {
            fill(kb + 1, (kb + 1) & 1);
            CP_COMMIT();
            asm volatile("cp.async.wait_group 1;" ::: "memory");
        } else {
            asm volatile("cp.async.wait_group 0;" ::: "memory");
        }
        __syncthreads();

        const uint32_t kbase = sKV + (kb & 1) * ASTAGE_B;

        // ---- S = Q K^T (3 passes) ----
        float sf[8][4];
#pragma unroll
        for (int i = 0; i < 8; i++)
#pragma unroll
            for (int e = 0; e < 4; e++) sf[i][e] = 0.0f;

#pragma unroll
        for (int ks = 0; ks < 4; ks++) {
            uint32_t kh4[4][4], kl4[4][4];
#pragma unroll
            for (int g = 0; g < 4; g++) {
                const int row = g * 16 + b_nloc;
                const uint32_t sw = SWZ((uint32_t)(row * 128 + ks * 32 + b_kh * 16));
                ldsm4(kh4[g], kbase + sw);
                ldsm4(kl4[g], kbase + KTILE_B + sw);
            }
#pragma unroll
            for (int nt = 0; nt < 8; nt++)
                mma16816(sf[nt], qh[ks], kh4[nt >> 1][(nt & 1) * 2],
                         kh4[nt >> 1][(nt & 1) * 2 + 1]);
#pragma unroll
            for (int nt = 0; nt < 8; nt++)
                mma16816(sf[nt], qh[ks], kl4[nt >> 1][(nt & 1) * 2],
                         kl4[nt >> 1][(nt & 1) * 2 + 1]);
#pragma unroll
            for (int nt = 0; nt < 8; nt++)
                mma16816(sf[nt], ql[ks], kh4[nt >> 1][(nt & 1) * 2],
                         kh4[nt >> 1][(nt & 1) * 2 + 1]);
        }

        // ---- online softmax ----
        const bool diag = (kb == qt);
#pragma unroll
        for (int half = 0; half < 2; half++) {
            const int rowg = qt * 64 + wid * 16 + (lane >> 2) + half * 8;
            float mx = -1e30f;
#pragma unroll
            for (int nt = 0; nt < 8; nt++)
#pragma unroll
                for (int e = 0; e < 2; e++) {
                    float v = sf[nt][half * 2 + e] * 0.125f;
                    if (diag) {
                        const int colg = kb * 64 + nt * 8 + (lane & 3) * 2 + e;
                        if (colg > rowg) v = -1e30f;
                    }
                    sf[nt][half * 2 + e] = v;
                    mx = fmaxf(mx, v);
                }
            mx = fmaxf(mx, __shfl_xor_sync(0xffffffffu, mx, 1));
            mx = fmaxf(mx, __shfl_xor_sync(0xffffffffu, mx, 2));
            const float m_new = fmaxf(m_run[half], mx);
            const float corr  = __expf(m_run[half] - m_new);
            float ls = 0.0f;
#pragma unroll
            for (int nt = 0; nt < 8; nt++)
#pragma unroll
                for (int e = 0; e < 2; e++) {
                    const float p = __expf(sf[nt][half * 2 + e] - m_new);
                    sf[nt][half * 2 + e] = p;
                    ls += p;
                }
            l_run[half] = l_run[half] * corr + ls;   // lane-partial
            m_run[half] = m_new;
#pragma unroll
            for (int dt = 0; dt < 8; dt++) {
                of[dt][half * 2]     *= corr;
                of[dt][half * 2 + 1] *= corr;
            }
        }

        // ---- O += P V (3 passes) ----
        const uint32_t vbase = kbase + 2 * KTILE_B;
#pragma unroll
        for (int kc = 0; kc < 4; kc++) {
            uint32_t pa_h[4], pa_l[4];
            pa_h[0] = pack_split(sf[kc * 2][0],     sf[kc * 2][1],     pa_l[0]);
            pa_h[1] = pack_split(sf[kc * 2][2],     sf[kc * 2][3],     pa_l[1]);
            pa_h[2] = pack_split(sf[kc * 2 + 1][0], sf[kc * 2 + 1][1], pa_l[2]);
            pa_h[3] = pack_split(sf[kc * 2 + 1][2], sf[kc * 2 + 1][3], pa_l[3]);

            uint32_t vh4[4][4], vl4[4][4];
#pragma unroll
            for (int dc = 0; dc < 4; dc++) {
                const int krow = kc * 16 + (lg & 1) * 8 + lr;
                const uint32_t sw =
                    SWZ((uint32_t)(krow * 128 + (dc * 16 + (lg >> 1) * 8) * 2));
                ldsm4t(vh4[dc], vbase + sw);
                ldsm4t(vl4[dc], vbase + KTILE_B + sw);
            }
#pragma unroll
            for (int dt = 0; dt < 8; dt++)
                mma16816(of[dt], pa_h, vh4[dt >> 1][(dt & 1) * 2],
                         vh4[dt >> 1][(dt & 1) * 2 + 1]);
#pragma unroll
            for (int dt = 0; dt < 8; dt++)
                mma16816(of[dt], pa_h, vl4[dt >> 1][(dt & 1) * 2],
                         vl4[dt >> 1][(dt & 1) * 2 + 1]);
#pragma unroll
            for (int dt = 0; dt < 8; dt++)
                mma16816(of[dt], pa_l, vh4[dt >> 1][(dt & 1) * 2],
                         vh4[dt >> 1][(dt & 1) * 2 + 1]);
        }
        __syncthreads();
    }

    // ---- epilogue ----
    float inv[2];
#pragma unroll
    for (int half = 0; half < 2; half++) {
        float l = l_run[half];
        l += __shfl_xor_sync(0xffffffffu, l, 1);
        l += __shfl_xor_sync(0xffffffffu, l, 2);
        inv[half] = 1.0f / l;
    }
    const size_t orow = qrow0 + wid * 16 + (lane >> 2);
    const size_t obase = orow * EMB + hoff + (lane & 3) * 2;
#pragma unroll
    for (int dt = 0; dt < 8; dt++) {
        uint32_t lo0, lo1;
        const uint32_t hi0 =
            pack_split(of[dt][0] * inv[0], of[dt][1] * inv[0], lo0);
        const uint32_t hi1 =
            pack_split(of[dt][2] * inv[1], of[dt][3] * inv[1], lo1);
        *(uint32_t*)(Yh + obase + dt * 8)           = hi0;
        *(uint32_t*)(Yl + obase + dt * 8)           = lo0;
        *(uint32_t*)(Yh + obase + 8 * EMB + dt * 8) = hi1;
        *(uint32_t*)(Yl + obase + 8 * EMB + dt * 8) = lo1;
    }
}

// ---------------------------------------------------------------------------
// Launch
// ---------------------------------------------------------------------------
extern "C" void kernel_launch(void* const* d_in, const int* in_sizes, int n_in,
                              void* d_out, int out_size)
{
    const float* x      = (const float*)d_in[0];
    const float* w_attn = (const float*)d_in[1];
    const float* b_attn = (const float*)d_in[2];
    const float* w_proj = (const float*)d_in[3];
    const float* b_proj = (const float*)d_in[4];
    float* out = (float*)d_out;

    void* p;
    cudaGetSymbolAddress(&p, g_x_h);    __nv_bfloat16* x_h   = (__nv_bfloat16*)p;
    cudaGetSymbolAddress(&p, g_x_l);    __nv_bfloat16* x_l   = (__nv_bfloat16*)p;
    cudaGetSymbolAddress(&p, g_wa_h);   __nv_bfloat16* wa_h  = (__nv_bfloat16*)p;
    cudaGetSymbolAddress(&p, g_wa_l);   __nv_bfloat16* wa_l  = (__nv_bfloat16*)p;
    cudaGetSymbolAddress(&p, g_wp_h);   __nv_bfloat16* wp_h  = (__nv_bfloat16*)p;
    cudaGetSymbolAddress(&p, g_wp_l);   __nv_bfloat16* wp_l  = (__nv_bfloat16*)p;
    cudaGetSymbolAddress(&p, g_qkv_h);  __nv_bfloat16* qkv_h = (__nv_bfloat16*)p;
    cudaGetSymbolAddress(&p, g_qkv_l);  __nv_bfloat16* qkv_l = (__nv_bfloat16*)p;
    cudaGetSymbolAddress(&p, g_y_h);    __nv_bfloat16* y_h   = (__nv_bfloat16*)p;
    cudaGetSymbolAddress(&p, g_y_l);    __nv_bfloat16* y_l   = (__nv_bfloat16*)p;

    cudaFuncSetAttribute(gemm_hmma<true>,
                         cudaFuncAttributeMaxDynamicSharedMemorySize, GSMEM);
    cudaFuncSetAttribute(gemm_hmma<false>,
                         cudaFuncAttributeMaxDynamicSharedMemorySize, GSMEM);
    cudaFuncSetAttribute(attn_hmma,
                         cudaFuncAttributeMaxDynamicSharedMemorySize, ASMEM);

    // 0) split inputs to (hi, lo) bf16
    {
        int n4 = MTOT * EMB / 4;
        split_kernel<<<n4 / 256, 256>>>((const float4*)x, (uint2*)x_h, (uint2*)x_l, n4);
        n4 = C3 * EMB / 4;
        split_kernel<<<n4 / 256, 256>>>((const float4*)w_attn, (uint2*)wa_h, (uint2*)wa_l, n4);
        n4 = EMB * EMB / 4;
        split_kernel<<<n4 / 256, 256>>>((const float4*)w_proj, (uint2*)wp_h, (uint2*)wp_l, n4);
    }

    // 1) qkv = x @ w_attn^T + b_attn, written directly as split bf16
    {
        dim3 grid(C3 / 128, MTOT / 128);
        gemm_hmma<true><<<grid, 512, GSMEM>>>(x_h, x_l, wa_h, wa_l, b_attn,
                                              nullptr, qkv_h, qkv_l,
                                              MTOT, C3, EMB);
    }

    // 2) HMMA flash attention -> split bf16 y
    {
        dim3 grid(SEQ / 64, HEADS, BATCH);
        attn_hmma<<<grid, 128, ASMEM>>>(qkv_h, qkv_l, y_h, y_l);
    }

    // 3) out = y @ w_proj^T + b_proj (fp32 out)
    {
        dim3 grid(EMB / 128, MTOT / 128);
        gemm_hmma<false><<<grid, 512, GSMEM>>>(y_h, y_l, wp_h, wp_l, b_proj,
                                               out, nullptr, nullptr,
                                               MTOT, EMB, EMB);
    }
}

// round 9
// speedup vs baseline: 1.0541x; 1.0541x over previous
#include <cuda_runtime.h>
#include <cuda_bf16.h>
#include <cstdint>

// Problem constants
#define BATCH 2
#define SEQ   2048
#define EMB   1024
#define HEADS 16
#define HDIM  64
#define C3    (3 * EMB)
#define MTOT  (BATCH * SEQ)   // 4096

// Scratch (allocation-free rule: __device__ globals)
__device__ __nv_bfloat16 g_x_h[MTOT * EMB];
__device__ __nv_bfloat16 g_x_l[MTOT * EMB];
__device__ __nv_bfloat16 g_wa_h[C3 * EMB];
__device__ __nv_bfloat16 g_wa_l[C3 * EMB];
__device__ __nv_bfloat16 g_wp_h[EMB * EMB];
__device__ __nv_bfloat16 g_wp_l[EMB * EMB];
__device__ __nv_bfloat16 g_qkv_h[MTOT * C3];
__device__ __nv_bfloat16 g_qkv_l[MTOT * C3];
__device__ __nv_bfloat16 g_y_h[MTOT * EMB];
__device__ __nv_bfloat16 g_y_l[MTOT * EMB];

// ---------------------------------------------------------------------------
// helpers (plain sm_80-level PTX: valid at compute_103)
// ---------------------------------------------------------------------------
__device__ __forceinline__ uint32_t smem_u32(const void* p) {
    uint32_t a;
    asm("{ .reg .u64 t; cvta.to.shared.u64 t, %1; cvt.u32.u64 %0, t; }"
        : "=r"(a) : "l"(p));
    return a;
}

__device__ __forceinline__ void cpasync16(uint32_t dst, const void* src) {
    asm volatile("cp.async.cg.shared.global [%0], [%1], 16;"
                 :: "r"(dst), "l"(src) : "memory");
}
#define CP_COMMIT() asm volatile("cp.async.commit_group;" ::: "memory")
#define CP_WAIT(n)  asm volatile("cp.async.wait_group %0;" :: "n"(n) : "memory")

__device__ __forceinline__ void ldsm4(uint32_t* r, uint32_t addr) {
    asm volatile("ldmatrix.sync.aligned.m8n8.x4.shared.b16 {%0,%1,%2,%3}, [%4];"
                 : "=r"(r[0]), "=r"(r[1]), "=r"(r[2]), "=r"(r[3]) : "r"(addr));
}
__device__ __forceinline__ void ldsm4t(uint32_t* r, uint32_t addr) {
    asm volatile("ldmatrix.sync.aligned.m8n8.x4.trans.shared.b16 {%0,%1,%2,%3}, [%4];"
                 : "=r"(r[0]), "=r"(r[1]), "=r"(r[2]), "=r"(r[3]) : "r"(addr));
}

__device__ __forceinline__ void mma16816(float* c, const uint32_t* a,
                                         uint32_t b0, uint32_t b1) {
    asm volatile(
        "mma.sync.aligned.m16n8k16.row.col.f32.bf16.bf16.f32 "
        "{%0,%1,%2,%3}, {%4,%5,%6,%7}, {%8,%9}, {%0,%1,%2,%3};"
        : "+f"(c[0]), "+f"(c[1]), "+f"(c[2]), "+f"(c[3])
        : "r"(a[0]), "r"(a[1]), "r"(a[2]), "r"(a[3]), "r"(b0), "r"(b1));
}

#define SWZ(o) ((o) ^ (((o) >> 3) & 0x70))

__device__ __forceinline__ uint32_t pack_split(float x, float y, uint32_t& lo) {
    __nv_bfloat162 h = __floats2bfloat162_rn(x, y);
    const float2 f = __bfloat1622float2(h);
    __nv_bfloat162 l = __floats2bfloat162_rn(x - f.x, y - f.y);
    lo = *(uint32_t*)&l;
    return *(uint32_t*)&h;
}

// ---------------------------------------------------------------------------
// split fp32 -> (hi, lo) bf16
// ---------------------------------------------------------------------------
__global__ __launch_bounds__(256) void split_kernel(
    const float4* __restrict__ in, uint2* __restrict__ hi,
    uint2* __restrict__ lo, int n4)
{
    const int i = blockIdx.x * 256 + threadIdx.x;
    if (i >= n4) return;
    const float4 v = in[i];
    __nv_bfloat162 h0 = __floats2bfloat162_rn(v.x, v.y);
    __nv_bfloat162 h1 = __floats2bfloat162_rn(v.z, v.w);
    const float2 f0 = __bfloat1622float2(h0);
    const float2 f1 = __bfloat1622float2(h1);
    __nv_bfloat162 l0 = __floats2bfloat162_rn(v.x - f0.x, v.y - f0.y);
    __nv_bfloat162 l1 = __floats2bfloat162_rn(v.z - f1.x, v.w - f1.y);
    hi[i] = make_uint2(*(uint32_t*)&h0, *(uint32_t*)&h1);
    lo[i] = make_uint2(*(uint32_t*)&l0, *(uint32_t*)&l1);
}

// ---------------------------------------------------------------------------
// HMMA NT GEMM: C = A @ B^T + bias (A,B pre-split bf16). 3-pass split accum.
// 256 threads, 8 warps (2x4), warp tile 64x32. CTA 128x128, BK=64.
// 3-stage cp.async ring, ONE __syncthreads per k-tile (CUTLASS mainloop order:
// wait -> barrier -> issue(kt+2) -> compute(kt)).
// ---------------------------------------------------------------------------
#define TILE_B  16384
#define STAGE_B (4 * TILE_B)            // 64 KB per stage
#define GSMEM   (3 * STAGE_B + 1024)    // 3 stages

template<bool SPLIT_OUT>
__global__ __launch_bounds__(256, 1) void gemm_hmma(
    const __nv_bfloat16* __restrict__ Ah, const __nv_bfloat16* __restrict__ Al,
    const __nv_bfloat16* __restrict__ Bh, const __nv_bfloat16* __restrict__ Bl,
    const float* __restrict__ bias, float* __restrict__ C,
    __nv_bfloat16* __restrict__ Ch, __nv_bfloat16* __restrict__ Cl,
    int M, int N, int K)
{
    extern __shared__ char smr[];
    const uint32_t sb = (smem_u32(smr) + 1023u) & ~1023u;

    const int t    = threadIdx.x;
    const int lane = t & 31;
    const int wid  = t >> 5;
    const int warp_m = wid & 1;     // 0..1 (64 rows each)
    const int warp_n = wid >> 1;    // 0..3 (32 cols each)
    const int bm = blockIdx.y * 128;
    const int bn = blockIdx.x * 128;

    const int lg = lane >> 3, lr = lane & 7;
    const int a_mloc = (lg & 1) * 8 + lr;  const int a_kh = lg >> 1;
    const int b_nloc = (lg >> 1) * 8 + lr; const int b_kh = lg & 1;

    const int NC = K >> 6;

    auto issue = [&](int kt, int stage) {
        const uint32_t base = sb + stage * STAGE_B;
        const int k0 = kt << 6;
#pragma unroll
        for (int l = 0; l < 4; l++) {
            const int idx = t + 256 * l;
            const int row = idx >> 3;
            const int ch  = idx & 7;
            const uint32_t sw = SWZ((uint32_t)(row * 128 + ch * 16));
            const size_t ga = (size_t)(bm + row) * K + k0 + ch * 8;
            const size_t gb = (size_t)(bn + row) * K + k0 + ch * 8;
            cpasync16(base + sw,              Ah + ga);
            cpasync16(base + TILE_B + sw,     Al + ga);
            cpasync16(base + 2 * TILE_B + sw, Bh + gb);
            cpasync16(base + 3 * TILE_B + sw, Bl + gb);
        }
    };

    float acc[4][4][4];
#pragma unroll
    for (int i = 0; i < 4; i++)
#pragma unroll
        for (int j = 0; j < 4; j++)
#pragma unroll
            for (int e = 0; e < 4; e++) acc[i][j][e] = 0.0f;

    issue(0, 0); CP_COMMIT();
    issue(1, 1); CP_COMMIT();

    int stage = 0;
    for (int kt = 0; kt < NC; kt++) {
        if (kt + 1 < NC) { CP_WAIT(1); } else { CP_WAIT(0); }
        __syncthreads();
        if (kt + 2 < NC) {
            int ns = stage + 2; if (ns >= 3) ns -= 3;
            issue(kt + 2, ns);
            CP_COMMIT();
        }

        const uint32_t base = sb + stage * STAGE_B;
#pragma unroll
        for (int ks = 0; ks < 4; ks++) {
            uint32_t ah[4][4], al[4][4], bh[2][4], bl[2][4];
#pragma unroll
            for (int mt = 0; mt < 4; mt++) {
                const int row = warp_m * 64 + mt * 16 + a_mloc;
                const uint32_t sw = SWZ((uint32_t)(row * 128 + ks * 32 + a_kh * 16));
                ldsm4(ah[mt], base + sw);
                ldsm4(al[mt], base + TILE_B + sw);
            }
#pragma unroll
            for (int np = 0; np < 2; np++) {
                const int row = warp_n * 32 + np * 16 + b_nloc;
                const uint32_t sw = SWZ((uint32_t)(row * 128 + ks * 32 + b_kh * 16));
                ldsm4(bh[np], base + 2 * TILE_B + sw);
                ldsm4(bl[np], base + 3 * TILE_B + sw);
            }
#pragma unroll
            for (int mt = 0; mt < 4; mt++)
#pragma unroll
                for (int nt = 0; nt < 4; nt++)
                    mma16816(acc[mt][nt], ah[mt],
                             bh[nt >> 1][(nt & 1) * 2], bh[nt >> 1][(nt & 1) * 2 + 1]);
#pragma unroll
            for (int mt = 0; mt < 4; mt++)
#pragma unroll
                for (int nt = 0; nt < 4; nt++)
                    mma16816(acc[mt][nt], ah[mt],
                             bl[nt >> 1][(nt & 1) * 2], bl[nt >> 1][(nt & 1) * 2 + 1]);
#pragma unroll
            for (int mt = 0; mt < 4; mt++)
#pragma unroll
                for (int nt = 0; nt < 4; nt++)
                    mma16816(acc[mt][nt], al[mt],
                             bh[nt >> 1][(nt & 1) * 2], bh[nt >> 1][(nt & 1) * 2 + 1]);
        }
        if (++stage >= 3) stage = 0;
    }

#pragma unroll
    for (int mt = 0; mt < 4; mt++) {
        const int row = bm + warp_m * 64 + mt * 16 + (lane >> 2);
#pragma unroll
        for (int nt = 0; nt < 4; nt++) {
            const int col = bn + warp_n * 32 + nt * 8 + (lane & 3) * 2;
            const float2 bb = *(const float2*)(bias + col);
            const float c00 = acc[mt][nt][0] + bb.x;
            const float c01 = acc[mt][nt][1] + bb.y;
            const float c10 = acc[mt][nt][2] + bb.x;
            const float c11 = acc[mt][nt][3] + bb.y;
            if (SPLIT_OUT) {
                uint32_t lo0, lo1;
                const uint32_t hi0 = pack_split(c00, c01, lo0);
                const uint32_t hi1 = pack_split(c10, c11, lo1);
                *(uint32_t*)(Ch + (size_t)row * N + col)       = hi0;
                *(uint32_t*)(Cl + (size_t)row * N + col)       = lo0;
                *(uint32_t*)(Ch + (size_t)(row + 8) * N + col) = hi1;
                *(uint32_t*)(Cl + (size_t)(row + 8) * N + col) = lo1;
            } else {
                *(float2*)(C + (size_t)row * N + col)       = make_float2(c00, c01);
                *(float2*)(C + (size_t)(row + 8) * N + col) = make_float2(c10, c11);
            }
        }
    }
}

// ---------------------------------------------------------------------------
// HMMA flash attention. CTA: 64 q-rows x (head, batch), 128 threads (4 warps
// x 16 rows), 2 CTAs/SM. k-blocks of 64, 2-stage ring, ONE barrier per kb:
// [fill(kb+1) -> compute(kb) -> wait+sync].
// ---------------------------------------------------------------------------
#define KTILE_B   8192           // 64 rows * 128 B
#define ASTAGE_B  (4 * KTILE_B)  // 32 KB
#define ASMEM     (16384 + 2 * ASTAGE_B + 1024)

__global__ __launch_bounds__(128, 2) void attn_hmma(
    const __nv_bfloat16* __restrict__ Gh, const __nv_bfloat16* __restrict__ Gl,
    __nv_bfloat16* __restrict__ Yh, __nv_bfloat16* __restrict__ Yl)
{
    extern __shared__ char smr[];
    const uint32_t sb  = (smem_u32(smr) + 1023u) & ~1023u;
    const uint32_t sQh = sb;
    const uint32_t sQl = sb + 8192;
    const uint32_t sKV = sb + 16384;

    const int t = threadIdx.x;
    const int lane = t & 31, wid = t >> 5;
    const int lg = lane >> 3, lr = lane & 7;
    const int a_mloc = (lg & 1) * 8 + lr, a_kh = lg >> 1;
    const int b_nloc = (lg >> 1) * 8 + lr, b_kh = lg & 1;

    const int qt = gridDim.x - 1 - blockIdx.x;   // heaviest first
    const int h  = blockIdx.y;
    const int b  = blockIdx.z;

    const size_t qrow0 = (size_t)b * SEQ + qt * 64;
    const size_t hoff  = (size_t)h * HDIM;

    auto fill = [&](int kb, int st) {
        const uint32_t base = sKV + st * ASTAGE_B;
#pragma unroll
        for (int l = 0; l < 4; l++) {
            const int idx = t + 128 * l;
            const int row = idx >> 3, ch = idx & 7;
            const uint32_t sw = SWZ((uint32_t)(row * 128 + ch * 16));
            const size_t g = ((size_t)b * SEQ + kb * 64 + row) * C3 + hoff + ch * 8;
            cpasync16(base + sw,               Gh + g + EMB);       // Kh
            cpasync16(base + KTILE_B + sw,     Gl + g + EMB);       // Kl
            cpasync16(base + 2 * KTILE_B + sw, Gh + g + 2 * EMB);   // Vh
            cpasync16(base + 3 * KTILE_B + sw, Gl + g + 2 * EMB);   // Vl
        }
    };

    // prologue: Q tiles + KV block 0 in one group
#pragma unroll
    for (int l = 0; l < 4; l++) {
        const int idx = t + 128 * l;
        const int row = idx >> 3, ch = idx & 7;
        const uint32_t sw = SWZ((uint32_t)(row * 128 + ch * 16));
        const size_t g = (qrow0 + row) * C3 + hoff + ch * 8;
        cpasync16(sQh + sw, Gh + g);
        cpasync16(sQl + sw, Gl + g);
    }
    fill(0, 0);
    CP_COMMIT();
    CP_WAIT(0);
    __syncthreads();

    // Q fragments (registers, whole CTA lifetime)
    uint32_t qh[4][4], ql[4][4];
#pragma unroll
    for (int ks = 0; ks < 4; ks++) {
        const int row = wid * 16 + a_mloc;
        const uint32_t sw = SWZ((uint32_t)(row * 128 + ks * 32 + a_kh * 16));
        ldsm4(qh[ks], sQh + sw);
        ldsm4(ql[ks], sQl + sw);
    }

    float of[8][4];
#pragma unroll
    for (int i = 0; i < 8; i++)
#pragma unroll
        for (int e = 0; e < 4; e++) of[i][e] = 0.0f;
    float m_run[2] = {-1e30f, -1e30f};
    float l_run[2] = {0.0f, 0.0f};

    const int nkb = qt + 1;
    for (int kb = 0; kb < nkb; kb++) {
        // issue next KV block before computing this one (overlap)
        if (kb + 1 < nkb) {
            fill(kb + 1, (kb + 1) & 1);
            CP_COMMIT();
        }

        const uint32_t kbase = sKV + (kb & 1) * ASTAGE_B;

        // ---- S = Q K^T (3 passes) ----
        float sf[8][4];
#pragma unroll
        for (int i = 0; i < 8; i++)
#pragma unroll
            for (int e = 0; e < 4; e++) sf[i][e] = 0.0f;

#pragma unroll
        for (int ks = 0; ks < 4; ks++) {
            uint32_t kh4[4][4], kl4[4][4];
#pragma unroll
            for (int g = 0; g < 4; g++) {
                const int row = g * 16 + b_nloc;
                const uint32_t sw = SWZ((uint32_t)(row * 128 + ks * 32 + b_kh * 16));
                ldsm4(kh4[g], kbase + sw);
                ldsm4(kl4[g], kbase + KTILE_B + sw);
            }
#pragma unroll
            for (int nt = 0; nt < 8; nt++)
                mma16816(sf[nt], qh[ks], kh4[nt >> 1][(nt & 1) * 2],
                         kh4[nt >> 1][(nt & 1) * 2 + 1]);
#pragma unroll
            for (int nt = 0; nt < 8; nt++)
                mma16816(sf[nt], qh[ks], kl4[nt >> 1][(nt & 1) * 2],
                         kl4[nt >> 1][(nt & 1) * 2 + 1]);
#pragma unroll
            for (int nt = 0; nt < 8; nt++)
                mma16816(sf[nt], ql[ks], kh4[nt >> 1][(nt & 1) * 2],
                         kh4[nt >> 1][(nt & 1) * 2 + 1]);
        }

        // ---- online softmax ----
        const bool diag = (kb == qt);
#pragma unroll
        for (int half = 0; half < 2; half++) {
            const int rowg = qt * 64 + wid * 16 + (lane >> 2) + half * 8;
            float mx = -1e30f;
#pragma unroll
            for (int nt = 0; nt < 8; nt++)
#pragma unroll
                for (int e = 0; e < 2; e++) {
                    float v = sf[nt][half * 2 + e] * 0.125f;
                    if (diag) {
                        const int colg = kb * 64 + nt * 8 + (lane & 3) * 2 + e;
                        if (colg > rowg) v = -1e30f;
                    }
                    sf[nt][half * 2 + e] = v;
                    mx = fmaxf(mx, v);
                }
            mx = fmaxf(mx, __shfl_xor_sync(0xffffffffu, mx, 1));
            mx = fmaxf(mx, __shfl_xor_sync(0xffffffffu, mx, 2));
            const float m_new = fmaxf(m_run[half], mx);
            const float corr  = __expf(m_run[half] - m_new);
            float ls = 0.0f;
#pragma unroll
            for (int nt = 0; nt < 8; nt++)
#pragma unroll
                for (int e = 0; e < 2; e++) {
                    const float p = __expf(sf[nt][half * 2 + e] - m_new);
                    sf[nt][half * 2 + e] = p;
                    ls += p;
                }
            l_run[half] = l_run[half] * corr + ls;   // lane-partial
            m_run[half] = m_new;
#pragma unroll
            for (int dt = 0; dt < 8; dt++) {
                of[dt][half * 2]     *= corr;
                of[dt][half * 2 + 1] *= corr;
            }
        }

        // ---- O += P V (3 passes) ----
        const uint32_t vbase = kbase + 2 * KTILE_B;
#pragma unroll
        for (int kc = 0; kc < 4; kc++) {
            uint32_t pa_h[4], pa_l[4];
            pa_h[0] = pack_split(sf[kc * 2][0],     sf[kc * 2][1],     pa_l[0]);
            pa_h[1] = pack_split(sf[kc * 2][2],     sf[kc * 2][3],     pa_l[1]);
            pa_h[2] = pack_split(sf[kc * 2 + 1][0], sf[kc * 2 + 1][1], pa_l[2]);
            pa_h[3] = pack_split(sf[kc * 2 + 1][2], sf[kc * 2 + 1][3], pa_l[3]);

            uint32_t vh4[4][4], vl4[4][4];
#pragma unroll
            for (int dc = 0; dc < 4; dc++) {
                const int krow = kc * 16 + (lg & 1) * 8 + lr;
                const uint32_t sw =
                    SWZ((uint32_t)(krow * 128 + (dc * 16 + (lg >> 1) * 8) * 2));
                ldsm4t(vh4[dc], vbase + sw);
                ldsm4t(vl4[dc], vbase + KTILE_B + sw);
            }
#pragma unroll
            for (int dt = 0; dt < 8; dt++)
                mma16816(of[dt], pa_h, vh4[dt >> 1][(dt & 1) * 2],
                         vh4[dt >> 1][(dt & 1) * 2 + 1]);
#pragma unroll
            for (int dt = 0; dt < 8; dt++)
                mma16816(of[dt], pa_h, vl4[dt >> 1][(dt & 1) * 2],
                         vl4[dt >> 1][(dt & 1) * 2 + 1]);
#pragma unroll
            for (int dt = 0; dt < 8; dt++)
                mma16816(of[dt], pa_l, vh4[dt >> 1][(dt & 1) * 2],
                         vh4[dt >> 1][(dt & 1) * 2 + 1]);
        }

        // stage kb fully consumed; make stage kb+1 visible, protect overwrite
        if (kb + 1 < nkb) {
            CP_WAIT(0);
            __syncthreads();
        }
    }

    // ---- epilogue ----
    float inv[2];
#pragma unroll
    for (int half = 0; half < 2; half++) {
        float l = l_run[half];
        l += __shfl_xor_sync(0xffffffffu, l, 1);
        l += __shfl_xor_sync(0xffffffffu, l, 2);
        inv[half] = 1.0f / l;
    }
    const size_t orow = qrow0 + wid * 16 + (lane >> 2);
    const size_t obase = orow * EMB + hoff + (lane & 3) * 2;
#pragma unroll
    for (int dt = 0; dt < 8; dt++) {
        uint32_t lo0, lo1;
        const uint32_t hi0 =
            pack_split(of[dt][0] * inv[0], of[dt][1] * inv[0], lo0);
        const uint32_t hi1 =
            pack_split(of[dt][2] * inv[1], of[dt][3] * inv[1], lo1);
        *(uint32_t*)(Yh + obase + dt * 8)           = hi0;
        *(uint32_t*)(Yl + obase + dt * 8)           = lo0;
        *(uint32_t*)(Yh + obase + 8 * EMB + dt * 8) = hi1;
        *(uint32_t*)(Yl + obase + 8 * EMB + dt * 8) = lo1;
    }
}

// ---------------------------------------------------------------------------
// Launch
// ---------------------------------------------------------------------------
extern "C" void kernel_launch(void* const* d_in, const int* in_sizes, int n_in,
                              void* d_out, int out_size)
{
    const float* x      = (const float*)d_in[0];
    const float* w_attn = (const float*)d_in[1];
    const float* b_attn = (const float*)d_in[2];
    const float* w_proj = (const float*)d_in[3];
    const float* b_proj = (const float*)d_in[4];
    float* out = (float*)d_out;

    void* p;
    cudaGetSymbolAddress(&p, g_x_h);    __nv_bfloat16* x_h   = (__nv_bfloat16*)p;
    cudaGetSymbolAddress(&p, g_x_l);    __nv_bfloat16* x_l   = (__nv_bfloat16*)p;
    cudaGetSymbolAddress(&p, g_wa_h);   __nv_bfloat16* wa_h  = (__nv_bfloat16*)p;
    cudaGetSymbolAddress(&p, g_wa_l);   __nv_bfloat16* wa_l  = (__nv_bfloat16*)p;
    cudaGetSymbolAddress(&p, g_wp_h);   __nv_bfloat16* wp_h  = (__nv_bfloat16*)p;
    cudaGetSymbolAddress(&p, g_wp_l);   __nv_bfloat16* wp_l  = (__nv_bfloat16*)p;
    cudaGetSymbolAddress(&p, g_qkv_h);  __nv_bfloat16* qkv_h = (__nv_bfloat16*)p;
    cudaGetSymbolAddress(&p, g_qkv_l);  __nv_bfloat16* qkv_l = (__nv_bfloat16*)p;
    cudaGetSymbolAddress(&p, g_y_h);    __nv_bfloat16* y_h   = (__nv_bfloat16*)p;
    cudaGetSymbolAddress(&p, g_y_l);    __nv_bfloat16* y_l   = (__nv_bfloat16*)p;

    cudaFuncSetAttribute(gemm_hmma<true>,
                         cudaFuncAttributeMaxDynamicSharedMemorySize, GSMEM);
    cudaFuncSetAttribute(gemm_hmma<false>,
                         cudaFuncAttributeMaxDynamicSharedMemorySize, GSMEM);
    cudaFuncSetAttribute(attn_hmma,
                         cudaFuncAttributeMaxDynamicSharedMemorySize, ASMEM);

    // 0) split inputs to (hi, lo) bf16
    {
        int n4 = MTOT * EMB / 4;
        split_kernel<<<n4 / 256, 256>>>((const float4*)x, (uint2*)x_h, (uint2*)x_l, n4);
        n4 = C3 * EMB / 4;
        split_kernel<<<n4 / 256, 256>>>((const float4*)w_attn, (uint2*)wa_h, (uint2*)wa_l, n4);
        n4 = EMB * EMB / 4;
        split_kernel<<<n4 / 256, 256>>>((const float4*)w_proj, (uint2*)wp_h, (uint2*)wp_l, n4);
    }

    // 1) qkv = x @ w_attn^T + b_attn, written directly as split bf16
    {
        dim3 grid(C3 / 128, MTOT / 128);
        gemm_hmma<true><<<grid, 256, GSMEM>>>(x_h, x_l, wa_h, wa_l, b_attn,
                                              nullptr, qkv_h, qkv_l,
                                              MTOT, C3, EMB);
    }

    // 2) HMMA flash attention -> split bf16 y
    {
        dim3 grid(SEQ / 64, HEADS, BATCH);
        attn_hmma<<<grid, 128, ASMEM>>>(qkv_h, qkv_l, y_h, y_l);
    }

    // 3) out = y @ w_proj^T + b_proj (fp32 out)
    {
        dim3 grid(EMB / 128, MTOT / 128);
        gemm_hmma<false><<<grid, 256, GSMEM>>>(y_h, y_l, wp_h, wp_l, b_proj,
                                               out, nullptr, nullptr,
                                               MTOT, EMB, EMB);
    }
}

// round 10
// speedup vs baseline: 1.3975x; 1.3258x over previous
#include <cuda_runtime.h>
#include <cuda_fp16.h>
#include <cstdint>

// Problem constants
#define BATCH 2
#define SEQ   2048
#define EMB   1024
#define HEADS 16
#define HDIM  64
#define C3    (3 * EMB)
#define MTOT  (BATCH * SEQ)   // 4096

// Scratch (allocation-free rule: __device__ globals), fp16 split operands
__device__ __half g_x_h[MTOT * EMB];
__device__ __half g_x_l[MTOT * EMB];
__device__ __half g_wa_h[C3 * EMB];
__device__ __half g_wa_l[C3 * EMB];      // written, unused (B is single-pass)
__device__ __half g_wp_h[EMB * EMB];
__device__ __half g_wp_l[EMB * EMB];     // written, unused
__device__ __half g_qkv_h[MTOT * C3];
__device__ __half g_qkv_l[MTOT * C3];    // lo used for Q only
__device__ __half g_y_h[MTOT * EMB];
__device__ __half g_y_l[MTOT * EMB];

// ---------------------------------------------------------------------------
// helpers (plain sm_80-level PTX: valid at compute_103)
// ---------------------------------------------------------------------------
__device__ __forceinline__ uint32_t smem_u32(const void* p) {
    uint32_t a;
    asm("{ .reg .u64 t; cvta.to.shared.u64 t, %1; cvt.u32.u64 %0, t; }"
        : "=r"(a) : "l"(p));
    return a;
}

__device__ __forceinline__ void cpasync16(uint32_t dst, const void* src) {
    asm volatile("cp.async.cg.shared.global [%0], [%1], 16;"
                 :: "r"(dst), "l"(src) : "memory");
}
#define CP_COMMIT() asm volatile("cp.async.commit_group;" ::: "memory")
#define CP_WAIT(n)  asm volatile("cp.async.wait_group %0;" :: "n"(n) : "memory")

__device__ __forceinline__ void ldsm4(uint32_t* r, uint32_t addr) {
    asm volatile("ldmatrix.sync.aligned.m8n8.x4.shared.b16 {%0,%1,%2,%3}, [%4];"
                 : "=r"(r[0]), "=r"(r[1]), "=r"(r[2]), "=r"(r[3]) : "r"(addr));
}
__device__ __forceinline__ void ldsm4t(uint32_t* r, uint32_t addr) {
    asm volatile("ldmatrix.sync.aligned.m8n8.x4.trans.shared.b16 {%0,%1,%2,%3}, [%4];"
                 : "=r"(r[0]), "=r"(r[1]), "=r"(r[2]), "=r"(r[3]) : "r"(addr));
}

__device__ __forceinline__ void mma16816(float* c, const uint32_t* a,
                                         uint32_t b0, uint32_t b1) {
    asm volatile(
        "mma.sync.aligned.m16n8k16.row.col.f32.f16.f16.f32 "
        "{%0,%1,%2,%3}, {%4,%5,%6,%7}, {%8,%9}, {%0,%1,%2,%3};"
        : "+f"(c[0]), "+f"(c[1]), "+f"(c[2]), "+f"(c[3])
        : "r"(a[0]), "r"(a[1]), "r"(a[2]), "r"(a[3]), "r"(b0), "r"(b1));
}

#define SWZ(o) ((o) ^ (((o) >> 3) & 0x70))

// fp32 pair -> packed f16x2 hi (return) + lo residual (out param)
__device__ __forceinline__ uint32_t pack_split(float x, float y, uint32_t& lo) {
    __half2 h = __float22half2_rn(make_float2(x, y));
    const float2 f = __half22float2(h);
    __half2 l = __float22half2_rn(make_float2(x - f.x, y - f.y));
    lo = *(uint32_t*)&l;
    return *(uint32_t*)&h;
}

// ---------------------------------------------------------------------------
// split fp32 -> (hi, lo) fp16
// ---------------------------------------------------------------------------
__global__ __launch_bounds__(256) void split_kernel(
    const float4* __restrict__ in, uint2* __restrict__ hi,
    uint2* __restrict__ lo, int n4)
{
    const int i = blockIdx.x * 256 + threadIdx.x;
    if (i >= n4) return;
    const float4 v = in[i];
    uint32_t l0, l1;
    const uint32_t h0 = pack_split(v.x, v.y, l0);
    const uint32_t h1 = pack_split(v.z, v.w, l1);
    hi[i] = make_uint2(h0, h1);
    lo[i] = make_uint2(l0, l1);
}

// ---------------------------------------------------------------------------
// HMMA NT GEMM, fp16 2-pass: C = (Ah+Al) @ Bh^T + bias.
// 256 threads, 8 warps (2x4), warp tile 64x32. CTA 128x128, BK=64.
// 3-stage cp.async ring, one __syncthreads per k-tile.
// Stage = 3 tiles (Ah, Al, Bh) x 16KB = 48KB.
// ---------------------------------------------------------------------------
#define TILE_B  16384
#define STAGE_B (3 * TILE_B)            // 48 KB per stage
#define GSMEM   (3 * STAGE_B + 1024)    // 3 stages

template<bool SPLIT_OUT>
__global__ __launch_bounds__(256, 1) void gemm_hmma(
    const __half* __restrict__ Ah, const __half* __restrict__ Al,
    const __half* __restrict__ Bh,
    const float* __restrict__ bias, float* __restrict__ C,
    __half* __restrict__ Ch, __half* __restrict__ Cl,
    int M, int N, int K)
{
    extern __shared__ char smr[];
    const uint32_t sb = (smem_u32(smr) + 1023u) & ~1023u;

    const int t    = threadIdx.x;
    const int lane = t & 31;
    const int wid  = t >> 5;
    const int warp_m = wid & 1;     // 0..1 (64 rows each)
    const int warp_n = wid >> 1;    // 0..3 (32 cols each)
    const int bm = blockIdx.y * 128;
    const int bn = blockIdx.x * 128;

    const int lg = lane >> 3, lr = lane & 7;
    const int a_mloc = (lg & 1) * 8 + lr;  const int a_kh = lg >> 1;
    const int b_nloc = (lg >> 1) * 8 + lr; const int b_kh = lg & 1;

    const int NC = K >> 6;

    auto issue = [&](int kt, int stage) {
        const uint32_t base = sb + stage * STAGE_B;
        const int k0 = kt << 6;
#pragma unroll
        for (int l = 0; l < 4; l++) {
            const int idx = t + 256 * l;
            const int row = idx >> 3;
            const int ch  = idx & 7;
            const uint32_t sw = SWZ((uint32_t)(row * 128 + ch * 16));
            const size_t ga = (size_t)(bm + row) * K + k0 + ch * 8;
            const size_t gb = (size_t)(bn + row) * K + k0 + ch * 8;
            cpasync16(base + sw,              Ah + ga);
            cpasync16(base + TILE_B + sw,     Al + ga);
            cpasync16(base + 2 * TILE_B + sw, Bh + gb);
        }
    };

    float acc[4][4][4];
#pragma unroll
    for (int i = 0; i < 4; i++)
#pragma unroll
        for (int j = 0; j < 4; j++)
#pragma unroll
            for (int e = 0; e < 4; e++) acc[i][j][e] = 0.0f;

    issue(0, 0); CP_COMMIT();
    issue(1, 1); CP_COMMIT();

    int stage = 0;
    for (int kt = 0; kt < NC; kt++) {
        if (kt + 1 < NC) { CP_WAIT(1); } else { CP_WAIT(0); }
        __syncthreads();
        if (kt + 2 < NC) {
            int ns = stage + 2; if (ns >= 3) ns -= 3;
            issue(kt + 2, ns);
            CP_COMMIT();
        }

        const uint32_t base = sb + stage * STAGE_B;
#pragma unroll
        for (int ks = 0; ks < 4; ks++) {
            uint32_t ah[4][4], al[4][4], bh[2][4];
#pragma unroll
            for (int mt = 0; mt < 4; mt++) {
                const int row = warp_m * 64 + mt * 16 + a_mloc;
                const uint32_t sw = SWZ((uint32_t)(row * 128 + ks * 32 + a_kh * 16));
                ldsm4(ah[mt], base + sw);
                ldsm4(al[mt], base + TILE_B + sw);
            }
#pragma unroll
            for (int np = 0; np < 2; np++) {
                const int row = warp_n * 32 + np * 16 + b_nloc;
                const uint32_t sw = SWZ((uint32_t)(row * 128 + ks * 32 + b_kh * 16));
                ldsm4(bh[np], base + 2 * TILE_B + sw);
            }
            // pass 1: Ah*Bh
#pragma unroll
            for (int mt = 0; mt < 4; mt++)
#pragma unroll
                for (int nt = 0; nt < 4; nt++)
                    mma16816(acc[mt][nt], ah[mt],
                             bh[nt >> 1][(nt & 1) * 2], bh[nt >> 1][(nt & 1) * 2 + 1]);
            // pass 2: Al*Bh
#pragma unroll
            for (int mt = 0; mt < 4; mt++)
#pragma unroll
                for (int nt = 0; nt < 4; nt++)
                    mma16816(acc[mt][nt], al[mt],
                             bh[nt >> 1][(nt & 1) * 2], bh[nt >> 1][(nt & 1) * 2 + 1]);
        }
        if (++stage >= 3) stage = 0;
    }

#pragma unroll
    for (int mt = 0; mt < 4; mt++) {
        const int row = bm + warp_m * 64 + mt * 16 + (lane >> 2);
#pragma unroll
        for (int nt = 0; nt < 4; nt++) {
            const int col = bn + warp_n * 32 + nt * 8 + (lane & 3) * 2;
            const float2 bb = *(const float2*)(bias + col);
            const float c00 = acc[mt][nt][0] + bb.x;
            const float c01 = acc[mt][nt][1] + bb.y;
            const float c10 = acc[mt][nt][2] + bb.x;
            const float c11 = acc[mt][nt][3] + bb.y;
            if (SPLIT_OUT) {
                uint32_t lo0, lo1;
                const uint32_t hi0 = pack_split(c00, c01, lo0);
                const uint32_t hi1 = pack_split(c10, c11, lo1);
                *(uint32_t*)(Ch + (size_t)row * N + col)       = hi0;
                *(uint32_t*)(Cl + (size_t)row * N + col)       = lo0;
                *(uint32_t*)(Ch + (size_t)(row + 8) * N + col) = hi1;
                *(uint32_t*)(Cl + (size_t)(row + 8) * N + col) = lo1;
            } else {
                *(float2*)(C + (size_t)row * N + col)       = make_float2(c00, c01);
                *(float2*)(C + (size_t)(row + 8) * N + col) = make_float2(c10, c11);
            }
        }
    }
}

// ---------------------------------------------------------------------------
// HMMA flash attention, fp16 2-pass. CTA: 64 q-rows x (head, batch),
// 128 threads (4 warps x 16 rows), 3 CTAs/SM (~49KB smem).
// S = (Qh+Ql) Kh^T; PV = (Ph+Pl) Vh. k-blocks of 64, 2-stage ring,
// one barrier per kb.
// ---------------------------------------------------------------------------
#define KTILE_B   8192           // 64 rows * 128 B
#define ASTAGE_B  (2 * KTILE_B)  // Kh + Vh = 16 KB
#define ASMEM     (16384 + 2 * ASTAGE_B + 1024)

__global__ __launch_bounds__(128, 3) void attn_hmma(
    const __half* __restrict__ Gh, const __half* __restrict__ Gl,
    __half* __restrict__ Yh, __half* __restrict__ Yl)
{
    extern __shared__ char smr[];
    const uint32_t sb  = (smem_u32(smr) + 1023u) & ~1023u;
    const uint32_t sQh = sb;
    const uint32_t sQl = sb + 8192;
    const uint32_t sKV = sb + 16384;

    const int t = threadIdx.x;
    const int lane = t & 31, wid = t >> 5;
    const int lg = lane >> 3, lr = lane & 7;
    const int a_mloc = (lg & 1) * 8 + lr, a_kh = lg >> 1;
    const int b_nloc = (lg >> 1) * 8 + lr, b_kh = lg & 1;

    const int qt = gridDim.x - 1 - blockIdx.x;   // heaviest first
    const int h  = blockIdx.y;
    const int b  = blockIdx.z;

    const size_t qrow0 = (size_t)b * SEQ + qt * 64;
    const size_t hoff  = (size_t)h * HDIM;

    auto fill = [&](int kb, int st) {
        const uint32_t base = sKV + st * ASTAGE_B;
#pragma unroll
        for (int l = 0; l < 4; l++) {
            const int idx = t + 128 * l;
            const int row = idx >> 3, ch = idx & 7;
            const uint32_t sw = SWZ((uint32_t)(row * 128 + ch * 16));
            const size_t g = ((size_t)b * SEQ + kb * 64 + row) * C3 + hoff + ch * 8;
            cpasync16(base + sw,           Gh + g + EMB);       // Kh
            cpasync16(base + KTILE_B + sw, Gh + g + 2 * EMB);   // Vh
        }
    };

    // prologue: Q tiles (hi+lo) + KV block 0 in one group
#pragma unroll
    for (int l = 0; l < 4; l++) {
        const int idx = t + 128 * l;
        const int row = idx >> 3, ch = idx & 7;
        const uint32_t sw = SWZ((uint32_t)(row * 128 + ch * 16));
        const size_t g = (qrow0 + row) * C3 + hoff + ch * 8;
        cpasync16(sQh + sw, Gh + g);
        cpasync16(sQl + sw, Gl + g);
    }
    fill(0, 0);
    CP_COMMIT();
    CP_WAIT(0);
    __syncthreads();

    // Q fragments (registers, whole CTA lifetime)
    uint32_t qh[4][4], ql[4][4];
#pragma unroll
    for (int ks = 0; ks < 4; ks++) {
        const int row = wid * 16 + a_mloc;
        const uint32_t sw = SWZ((uint32_t)(row * 128 + ks * 32 + a_kh * 16));
        ldsm4(qh[ks], sQh + sw);
        ldsm4(ql[ks], sQl + sw);
    }

    float of[8][4];
#pragma unroll
    for (int i = 0; i < 8; i++)
#pragma unroll
        for (int e = 0; e < 4; e++) of[i][e] = 0.0f;
    float m_run[2] = {-1e30f, -1e30f};
    float l_run[2] = {0.0f, 0.0f};

    const int nkb = qt + 1;
    for (int kb = 0; kb < nkb; kb++) {
        // issue next KV block before computing this one (overlap)
        if (kb + 1 < nkb) {
            fill(kb + 1, (kb + 1) & 1);
            CP_COMMIT();
        }

        const uint32_t kbase = sKV + (kb & 1) * ASTAGE_B;

        // ---- S = Q K^T (2 passes: Qh*Kh, Ql*Kh) ----
        float sf[8][4];
#pragma unroll
        for (int i = 0; i < 8; i++)
#pragma unroll
            for (int e = 0; e < 4; e++) sf[i][e] = 0.0f;

#pragma unroll
        for (int ks = 0; ks < 4; ks++) {
            uint32_t kh4[4][4];
#pragma unroll
            for (int g = 0; g < 4; g++) {
                const int row = g * 16 + b_nloc;
                const uint32_t sw = SWZ((uint32_t)(row * 128 + ks * 32 + b_kh * 16));
                ldsm4(kh4[g], kbase + sw);
            }
#pragma unroll
            for (int nt = 0; nt < 8; nt++)
                mma16816(sf[nt], qh[ks], kh4[nt >> 1][(nt & 1) * 2],
                         kh4[nt >> 1][(nt & 1) * 2 + 1]);
#pragma unroll
            for (int nt = 0; nt < 8; nt++)
                mma16816(sf[nt], ql[ks], kh4[nt >> 1][(nt & 1) * 2],
                         kh4[nt >> 1][(nt & 1) * 2 + 1]);
        }

        // ---- online softmax ----
        const bool diag = (kb == qt);
#pragma unroll
        for (int half = 0; half < 2; half++) {
            const int rowg = qt * 64 + wid * 16 + (lane >> 2) + half * 8;
            float mx = -1e30f;
#pragma unroll
            for (int nt = 0; nt < 8; nt++)
#pragma unroll
                for (int e = 0; e < 2; e++) {
                    float v = sf[nt][half * 2 + e] * 0.125f;
                    if (diag) {
                        const int colg = kb * 64 + nt * 8 + (lane & 3) * 2 + e;
                        if (colg > rowg) v = -1e30f;
                    }
                    sf[nt][half * 2 + e] = v;
                    mx = fmaxf(mx, v);
                }
            mx = fmaxf(mx, __shfl_xor_sync(0xffffffffu, mx, 1));
            mx = fmaxf(mx, __shfl_xor_sync(0xffffffffu, mx, 2));
            const float m_new = fmaxf(m_run[half], mx);
            const float corr  = __expf(m_run[half] - m_new);
            float ls = 0.0f;
#pragma unroll
            for (int nt = 0; nt < 8; nt++)
#pragma unroll
                for (int e = 0; e < 2; e++) {
                    const float p = __expf(sf[nt][half * 2 + e] - m_new);
                    sf[nt][half * 2 + e] = p;
                    ls += p;
                }
            l_run[half] = l_run[half] * corr + ls;   // lane-partial
            m_run[half] = m_new;
#pragma unroll
            for (int dt = 0; dt < 8; dt++) {
                of[dt][half * 2]     *= corr;
                of[dt][half * 2 + 1] *= corr;
            }
        }

        // ---- O += P V (2 passes: Ph*Vh, Pl*Vh) ----
        const uint32_t vbase = kbase + KTILE_B;
#pragma unroll
        for (int kc = 0; kc < 4; kc++) {
            uint32_t pa_h[4], pa_l[4];
            pa_h[0] = pack_split(sf[kc * 2][0],     sf[kc * 2][1],     pa_l[0]);
            pa_h[1] = pack_split(sf[kc * 2][2],     sf[kc * 2][3],     pa_l[1]);
            pa_h[2] = pack_split(sf[kc * 2 + 1][0], sf[kc * 2 + 1][1], pa_l[2]);
            pa_h[3] = pack_split(sf[kc * 2 + 1][2], sf[kc * 2 + 1][3], pa_l[3]);

            uint32_t vh4[4][4];
#pragma unroll
            for (int dc = 0; dc < 4; dc++) {
                const int krow = kc * 16 + (lg & 1) * 8 + lr;
                const uint32_t sw =
                    SWZ((uint32_t)(krow * 128 + (dc * 16 + (lg >> 1) * 8) * 2));
                ldsm4t(vh4[dc], vbase + sw);
            }
#pragma unroll
            for (int dt = 0; dt < 8; dt++)
                mma16816(of[dt], pa_h, vh4[dt >> 1][(dt & 1) * 2],
                         vh4[dt >> 1][(dt & 1) * 2 + 1]);
#pragma unroll
            for (int dt = 0; dt < 8; dt++)
                mma16816(of[dt], pa_l, vh4[dt >> 1][(dt & 1) * 2],
                         vh4[dt >> 1][(dt & 1) * 2 + 1]);
        }

        // stage kb fully consumed; make stage kb+1 visible, protect overwrite
        if (kb + 1 < nkb) {
            CP_WAIT(0);
            __syncthreads();
        }
    }

    // ---- epilogue ----
    float inv[2];
#pragma unroll
    for (int half = 0; half < 2; half++) {
        float l = l_run[half];
        l += __shfl_xor_sync(0xffffffffu, l, 1);
        l += __shfl_xor_sync(0xffffffffu, l, 2);
        inv[half] = 1.0f / l;
    }
    const size_t orow = qrow0 + wid * 16 + (lane >> 2);
    const size_t obase = orow * EMB + hoff + (lane & 3) * 2;
#pragma unroll
    for (int dt = 0; dt < 8; dt++) {
        uint32_t lo0, lo1;
        const uint32_t hi0 =
            pack_split(of[dt][0] * inv[0], of[dt][1] * inv[0], lo0);
        const uint32_t hi1 =
            pack_split(of[dt][2] * inv[1], of[dt][3] * inv[1], lo1);
        *(uint32_t*)(Yh + obase + dt * 8)           = hi0;
        *(uint32_t*)(Yl + obase + dt * 8)           = lo0;
        *(uint32_t*)(Yh + obase + 8 * EMB + dt * 8) = hi1;
        *(uint32_t*)(Yl + obase + 8 * EMB + dt * 8) = lo1;
    }
}

// ---------------------------------------------------------------------------
// Launch
// ---------------------------------------------------------------------------
extern "C" void kernel_launch(void* const* d_in, const int* in_sizes, int n_in,
                              void* d_out, int out_size)
{
    const float* x      = (const float*)d_in[0];
    const float* w_attn = (const float*)d_in[1];
    const float* b_attn = (const float*)d_in[2];
    const float* w_proj = (const float*)d_in[3];
    const float* b_proj = (const float*)d_in[4];
    float* out = (float*)d_out;

    void* p;
    cudaGetSymbolAddress(&p, g_x_h);    __half* x_h   = (__half*)p;
    cudaGetSymbolAddress(&p, g_x_l);    __half* x_l   = (__half*)p;
    cudaGetSymbolAddress(&p, g_wa_h);   __half* wa_h  = (__half*)p;
    cudaGetSymbolAddress(&p, g_wa_l);   __half* wa_l  = (__half*)p;
    cudaGetSymbolAddress(&p, g_wp_h);   __half* wp_h  = (__half*)p;
    cudaGetSymbolAddress(&p, g_wp_l);   __half* wp_l  = (__half*)p;
    cudaGetSymbolAddress(&p, g_qkv_h);  __half* qkv_h = (__half*)p;
    cudaGetSymbolAddress(&p, g_qkv_l);  __half* qkv_l = (__half*)p;
    cudaGetSymbolAddress(&p, g_y_h);    __half* y_h   = (__half*)p;
    cudaGetSymbolAddress(&p, g_y_l);    __half* y_l   = (__half*)p;

    cudaFuncSetAttribute(gemm_hmma<true>,
                         cudaFuncAttributeMaxDynamicSharedMemorySize, GSMEM);
    cudaFuncSetAttribute(gemm_hmma<false>,
                         cudaFuncAttributeMaxDynamicSharedMemorySize, GSMEM);
    cudaFuncSetAttribute(attn_hmma,
                         cudaFuncAttributeMaxDynamicSharedMemorySize, ASMEM);

    // 0) split inputs to (hi, lo) fp16
    {
        int n4 = MTOT * EMB / 4;
        split_kernel<<<n4 / 256, 256>>>((const float4*)x, (uint2*)x_h, (uint2*)x_l, n4);
        n4 = C3 * EMB / 4;
        split_kernel<<<n4 / 256, 256>>>((const float4*)w_attn, (uint2*)wa_h, (uint2*)wa_l, n4);
        n4 = EMB * EMB / 4;
        split_kernel<<<n4 / 256, 256>>>((const float4*)w_proj, (uint2*)wp_h, (uint2*)wp_l, n4);
    }

    // 1) qkv = x @ w_attn^T + b_attn, written directly as split fp16
    {
        dim3 grid(C3 / 128, MTOT / 128);
        gemm_hmma<true><<<grid, 256, GSMEM>>>(x_h, x_l, wa_h, b_attn,
                                              nullptr, qkv_h, qkv_l,
                                              MTOT, C3, EMB);
    }

    // 2) HMMA flash attention -> split fp16 y
    {
        dim3 grid(SEQ / 64, HEADS, BATCH);
        attn_hmma<<<grid, 128, ASMEM>>>(qkv_h, qkv_l, y_h, y_l);
    }

    // 3) out = y @ w_proj^T + b_proj (fp32 out)
    {
        dim3 grid(EMB / 128, MTOT / 128);
        gemm_hmma<false><<<grid, 256, GSMEM>>>(y_h, y_l, wp_h, b_proj,
                                               out, nullptr, nullptr,
                                               MTOT, EMB, EMB);
    }
}

// round 11
// speedup vs baseline: 1.7052x; 1.2202x over previous
#include <cuda_runtime.h>
#include <cuda_fp16.h>
#include <cstdint>

// Problem constants
#define BATCH 2
#define SEQ   2048
#define EMB   1024
#define HEADS 16
#define HDIM  64
#define C3    (3 * EMB)
#define MTOT  (BATCH * SEQ)   // 4096

// Scratch (allocation-free rule: __device__ globals), fp16 split operands
__device__ __half g_x_h[MTOT * EMB];
__device__ __half g_x_l[MTOT * EMB];
__device__ __half g_wa_h[C3 * EMB];
__device__ __half g_wp_h[EMB * EMB];
__device__ __half g_qkv_h[MTOT * C3];
__device__ __half g_qkv_l[MTOT * C3];    // lo written/used for q columns only
__device__ __half g_y_h[MTOT * EMB];

// ---------------------------------------------------------------------------
// helpers (plain sm_80-level PTX: valid at compute_103)
// ---------------------------------------------------------------------------
__device__ __forceinline__ uint32_t smem_u32(const void* p) {
    uint32_t a;
    asm("{ .reg .u64 t; cvta.to.shared.u64 t, %1; cvt.u32.u64 %0, t; }"
        : "=r"(a) : "l"(p));
    return a;
}

__device__ __forceinline__ void cpasync16(uint32_t dst, const void* src) {
    asm volatile("cp.async.cg.shared.global [%0], [%1], 16;"
                 :: "r"(dst), "l"(src) : "memory");
}
#define CP_COMMIT() asm volatile("cp.async.commit_group;" ::: "memory")
#define CP_WAIT(n)  asm volatile("cp.async.wait_group %0;" :: "n"(n) : "memory")

__device__ __forceinline__ void ldsm4(uint32_t* r, uint32_t addr) {
    asm volatile("ldmatrix.sync.aligned.m8n8.x4.shared.b16 {%0,%1,%2,%3}, [%4];"
                 : "=r"(r[0]), "=r"(r[1]), "=r"(r[2]), "=r"(r[3]) : "r"(addr));
}
__device__ __forceinline__ void ldsm4t(uint32_t* r, uint32_t addr) {
    asm volatile("ldmatrix.sync.aligned.m8n8.x4.trans.shared.b16 {%0,%1,%2,%3}, [%4];"
                 : "=r"(r[0]), "=r"(r[1]), "=r"(r[2]), "=r"(r[3]) : "r"(addr));
}

__device__ __forceinline__ void mma16816(float* c, const uint32_t* a,
                                         uint32_t b0, uint32_t b1) {
    asm volatile(
        "mma.sync.aligned.m16n8k16.row.col.f32.f16.f16.f32 "
        "{%0,%1,%2,%3}, {%4,%5,%6,%7}, {%8,%9}, {%0,%1,%2,%3};"
        : "+f"(c[0]), "+f"(c[1]), "+f"(c[2]), "+f"(c[3])
        : "r"(a[0]), "r"(a[1]), "r"(a[2]), "r"(a[3]), "r"(b0), "r"(b1));
}

#define SWZ(o) ((o) ^ (((o) >> 3) & 0x70))

// fp32 pair -> packed f16x2 hi (return) + lo residual (out param)
__device__ __forceinline__ uint32_t pack_split(float x, float y, uint32_t& lo) {
    __half2 h = __float22half2_rn(make_float2(x, y));
    const float2 f = __half22float2(h);
    __half2 l = __float22half2_rn(make_float2(x - f.x, y - f.y));
    lo = *(uint32_t*)&l;
    return *(uint32_t*)&h;
}
__device__ __forceinline__ uint32_t pack_hi(float x, float y) {
    __half2 h = __float22half2_rn(make_float2(x, y));
    return *(uint32_t*)&h;
}

// ---------------------------------------------------------------------------
// split fp32 -> hi fp16 (+ optional lo residual)
// ---------------------------------------------------------------------------
__global__ __launch_bounds__(256) void split_kernel(
    const float4* __restrict__ in, uint2* __restrict__ hi,
    uint2* __restrict__ lo, int n4)
{
    const int i = blockIdx.x * 256 + threadIdx.x;
    if (i >= n4) return;
    const float4 v = in[i];
    uint32_t l0, l1;
    const uint32_t h0 = pack_split(v.x, v.y, l0);
    const uint32_t h1 = pack_split(v.z, v.w, l1);
    hi[i] = make_uint2(h0, h1);
    if (lo) lo[i] = make_uint2(l0, l1);
}

// ---------------------------------------------------------------------------
// HMMA NT GEMM, fp16, variable passes: C = (Ah [+ Al if bn<n_alo]) @ Bh^T + bias.
// 256 threads, 8 warps (2x4), warp tile 64x32. CTA 128x128, BK=64.
// 3-stage cp.async ring, one __syncthreads per k-tile.
// SPLIT_OUT: write fp16 hi (Ch) always + lo (Cl) for bn<n_alo; else fp32 C.
// ---------------------------------------------------------------------------
#define TILE_B  16384
#define STAGE_B (3 * TILE_B)            // Ah, Al, Bh slots (Al unused if !alo)
#define GSMEM   (3 * STAGE_B + 1024)

template<bool SPLIT_OUT>
__global__ __launch_bounds__(256, 1) void gemm_hmma(
    const __half* __restrict__ Ah, const __half* __restrict__ Al,
    const __half* __restrict__ Bh,
    const float* __restrict__ bias, float* __restrict__ C,
    __half* __restrict__ Ch, __half* __restrict__ Cl,
    int M, int N, int K, int n_alo)
{
    extern __shared__ char smr[];
    const uint32_t sb = (smem_u32(smr) + 1023u) & ~1023u;

    const int t    = threadIdx.x;
    const int lane = t & 31;
    const int wid  = t >> 5;
    const int warp_m = wid & 1;     // 0..1 (64 rows each)
    const int warp_n = wid >> 1;    // 0..3 (32 cols each)
    const int bm = blockIdx.y * 128;
    const int bn = blockIdx.x * 128;
    const bool alo = bn < n_alo;    // uniform per CTA

    const int lg = lane >> 3, lr = lane & 7;
    const int a_mloc = (lg & 1) * 8 + lr;  const int a_kh = lg >> 1;
    const int b_nloc = (lg >> 1) * 8 + lr; const int b_kh = lg & 1;

    const int NC = K >> 6;

    auto issue = [&](int kt, int stage) {
        const uint32_t base = sb + stage * STAGE_B;
        const int k0 = kt << 6;
#pragma unroll
        for (int l = 0; l < 4; l++) {
            const int idx = t + 256 * l;
            const int row = idx >> 3;
            const int ch  = idx & 7;
            const uint32_t sw = SWZ((uint32_t)(row * 128 + ch * 16));
            const size_t ga = (size_t)(bm + row) * K + k0 + ch * 8;
            const size_t gb = (size_t)(bn + row) * K + k0 + ch * 8;
            cpasync16(base + sw,              Ah + ga);
            if (alo) cpasync16(base + TILE_B + sw, Al + ga);
            cpasync16(base + 2 * TILE_B + sw, Bh + gb);
        }
    };

    float acc[4][4][4];
#pragma unroll
    for (int i = 0; i < 4; i++)
#pragma unroll
        for (int j = 0; j < 4; j++)
#pragma unroll
            for (int e = 0; e < 4; e++) acc[i][j][e] = 0.0f;

    issue(0, 0); CP_COMMIT();
    issue(1, 1); CP_COMMIT();

    int stage = 0;
    for (int kt = 0; kt < NC; kt++) {
        if (kt + 1 < NC) { CP_WAIT(1); } else { CP_WAIT(0); }
        __syncthreads();
        if (kt + 2 < NC) {
            int ns = stage + 2; if (ns >= 3) ns -= 3;
            issue(kt + 2, ns);
            CP_COMMIT();
        }

        const uint32_t base = sb + stage * STAGE_B;
#pragma unroll
        for (int ks = 0; ks < 4; ks++) {
            uint32_t ah[4][4], al[4][4], bh[2][4];
#pragma unroll
            for (int mt = 0; mt < 4; mt++) {
                const int row = warp_m * 64 + mt * 16 + a_mloc;
                const uint32_t sw = SWZ((uint32_t)(row * 128 + ks * 32 + a_kh * 16));
                ldsm4(ah[mt], base + sw);
                if (alo) ldsm4(al[mt], base + TILE_B + sw);
            }
#pragma unroll
            for (int np = 0; np < 2; np++) {
                const int row = warp_n * 32 + np * 16 + b_nloc;
                const uint32_t sw = SWZ((uint32_t)(row * 128 + ks * 32 + b_kh * 16));
                ldsm4(bh[np], base + 2 * TILE_B + sw);
            }
            // pass 1: Ah*Bh
#pragma unroll
            for (int mt = 0; mt < 4; mt++)
#pragma unroll
                for (int nt = 0; nt < 4; nt++)
                    mma16816(acc[mt][nt], ah[mt],
                             bh[nt >> 1][(nt & 1) * 2], bh[nt >> 1][(nt & 1) * 2 + 1]);
            // pass 2: Al*Bh (precision-critical columns only)
            if (alo) {
#pragma unroll
                for (int mt = 0; mt < 4; mt++)
#pragma unroll
                    for (int nt = 0; nt < 4; nt++)
                        mma16816(acc[mt][nt], al[mt],
                                 bh[nt >> 1][(nt & 1) * 2], bh[nt >> 1][(nt & 1) * 2 + 1]);
            }
        }
        if (++stage >= 3) stage = 0;
    }

#pragma unroll
    for (int mt = 0; mt < 4; mt++) {
        const int row = bm + warp_m * 64 + mt * 16 + (lane >> 2);
#pragma unroll
        for (int nt = 0; nt < 4; nt++) {
            const int col = bn + warp_n * 32 + nt * 8 + (lane & 3) * 2;
            const float2 bb = *(const float2*)(bias + col);
            const float c00 = acc[mt][nt][0] + bb.x;
            const float c01 = acc[mt][nt][1] + bb.y;
            const float c10 = acc[mt][nt][2] + bb.x;
            const float c11 = acc[mt][nt][3] + bb.y;
            if (SPLIT_OUT) {
                if (alo) {
                    uint32_t lo0, lo1;
                    const uint32_t hi0 = pack_split(c00, c01, lo0);
                    const uint32_t hi1 = pack_split(c10, c11, lo1);
                    *(uint32_t*)(Ch + (size_t)row * N + col)       = hi0;
                    *(uint32_t*)(Cl + (size_t)row * N + col)       = lo0;
                    *(uint32_t*)(Ch + (size_t)(row + 8) * N + col) = hi1;
                    *(uint32_t*)(Cl + (size_t)(row + 8) * N + col) = lo1;
                } else {
                    *(uint32_t*)(Ch + (size_t)row * N + col)       = pack_hi(c00, c01);
                    *(uint32_t*)(Ch + (size_t)(row + 8) * N + col) = pack_hi(c10, c11);
                }
            } else {
                *(float2*)(C + (size_t)row * N + col)       = make_float2(c00, c01);
                *(float2*)(C + (size_t)(row + 8) * N + col) = make_float2(c10, c11);
            }
        }
    }
}

// ---------------------------------------------------------------------------
// HMMA flash attention, fp16 2-pass (Q split, K/V single). CTA: 64 q-rows x
// (head, batch), 128 threads (4 warps x 16 rows), 3 CTAs/SM (~49KB smem).
// Output y written as single fp16 (hi only).
// ---------------------------------------------------------------------------
#define KTILE_B   8192           // 64 rows * 128 B
#define ASTAGE_B  (2 * KTILE_B)  // Kh + Vh = 16 KB
#define ASMEM     (16384 + 2 * ASTAGE_B + 1024)

__global__ __launch_bounds__(128, 3) void attn_hmma(
    const __half* __restrict__ Gh, const __half* __restrict__ Gl,
    __half* __restrict__ Yh)
{
    extern __shared__ char smr[];
    const uint32_t sb  = (smem_u32(smr) + 1023u) & ~1023u;
    const uint32_t sQh = sb;
    const uint32_t sQl = sb + 8192;
    const uint32_t sKV = sb + 16384;

    const int t = threadIdx.x;
    const int lane = t & 31, wid = t >> 5;
    const int lg = lane >> 3, lr = lane & 7;
    const int a_mloc = (lg & 1) * 8 + lr, a_kh = lg >> 1;
    const int b_nloc = (lg >> 1) * 8 + lr, b_kh = lg & 1;

    const int qt = gridDim.x - 1 - blockIdx.x;   // heaviest first
    const int h  = blockIdx.y;
    const int b  = blockIdx.z;

    const size_t qrow0 = (size_t)b * SEQ + qt * 64;
    const size_t hoff  = (size_t)h * HDIM;

    auto fill = [&](int kb, int st) {
        const uint32_t base = sKV + st * ASTAGE_B;
#pragma unroll
        for (int l = 0; l < 4; l++) {
            const int idx = t + 128 * l;
            const int row = idx >> 3, ch = idx & 7;
            const uint32_t sw = SWZ((uint32_t)(row * 128 + ch * 16));
            const size_t g = ((size_t)b * SEQ + kb * 64 + row) * C3 + hoff + ch * 8;
            cpasync16(base + sw,           Gh + g + EMB);       // Kh
            cpasync16(base + KTILE_B + sw, Gh + g + 2 * EMB);   // Vh
        }
    };

    // prologue: Q tiles (hi+lo) + KV block 0 in one group
#pragma unroll
    for (int l = 0; l < 4; l++) {
        const int idx = t + 128 * l;
        const int row = idx >> 3, ch = idx & 7;
        const uint32_t sw = SWZ((uint32_t)(row * 128 + ch * 16));
        const size_t g = (qrow0 + row) * C3 + hoff + ch * 8;
        cpasync16(sQh + sw, Gh + g);
        cpasync16(sQl + sw, Gl + g);
    }
    fill(0, 0);
    CP_COMMIT();
    CP_WAIT(0);
    __syncthreads();

    // Q fragments (registers, whole CTA lifetime)
    uint32_t qh[4][4], ql[4][4];
#pragma unroll
    for (int ks = 0; ks < 4; ks++) {
        const int row = wid * 16 + a_mloc;
        const uint32_t sw = SWZ((uint32_t)(row * 128 + ks * 32 + a_kh * 16));
        ldsm4(qh[ks], sQh + sw);
        ldsm4(ql[ks], sQl + sw);
    }

    float of[8][4];
#pragma unroll
    for (int i = 0; i < 8; i++)
#pragma unroll
        for (int e = 0; e < 4; e++) of[i][e] = 0.0f;
    float m_run[2] = {-1e30f, -1e30f};
    float l_run[2] = {0.0f, 0.0f};

    const int nkb = qt + 1;
    for (int kb = 0; kb < nkb; kb++) {
        if (kb + 1 < nkb) {
            fill(kb + 1, (kb + 1) & 1);
            CP_COMMIT();
        }

        const uint32_t kbase = sKV + (kb & 1) * ASTAGE_B;

        // ---- S = Q K^T (2 passes: Qh*Kh, Ql*Kh) ----
        float sf[8][4];
#pragma unroll
        for (int i = 0; i < 8; i++)
#pragma unroll
            for (int e = 0; e < 4; e++) sf[i][e] = 0.0f;

#pragma unroll
        for (int ks = 0; ks < 4; ks++) {
            uint32_t kh4[4][4];
#pragma unroll
            for (int g = 0; g < 4; g++) {
                const int row = g * 16 + b_nloc;
                const uint32_t sw = SWZ((uint32_t)(row * 128 + ks * 32 + b_kh * 16));
                ldsm4(kh4[g], kbase + sw);
            }
#pragma unroll
            for (int nt = 0; nt < 8; nt++)
                mma16816(sf[nt], qh[ks], kh4[nt >> 1][(nt & 1) * 2],
                         kh4[nt >> 1][(nt & 1) * 2 + 1]);
#pragma unroll
            for (int nt = 0; nt < 8; nt++)
                mma16816(sf[nt], ql[ks], kh4[nt >> 1][(nt & 1) * 2],
                         kh4[nt >> 1][(nt & 1) * 2 + 1]);
        }

        // ---- online softmax ----
        const bool diag = (kb == qt);
#pragma unroll
        for (int half = 0; half < 2; half++) {
            const int rowg = qt * 64 + wid * 16 + (lane >> 2) + half * 8;
            float mx = -1e30f;
#pragma unroll
            for (int nt = 0; nt < 8; nt++)
#pragma unroll
                for (int e = 0; e < 2; e++) {
                    float v = sf[nt][half * 2 + e] * 0.125f;
                    if (diag) {
                        const int colg = kb * 64 + nt * 8 + (lane & 3) * 2 + e;
                        if (colg > rowg) v = -1e30f;
                    }
                    sf[nt][half * 2 + e] = v;
                    mx = fmaxf(mx, v);
                }
            mx = fmaxf(mx, __shfl_xor_sync(0xffffffffu, mx, 1));
            mx = fmaxf(mx, __shfl_xor_sync(0xffffffffu, mx, 2));
            const float m_new = fmaxf(m_run[half], mx);
            const float corr  = __expf(m_run[half] - m_new);
            float ls = 0.0f;
#pragma unroll
            for (int nt = 0; nt < 8; nt++)
#pragma unroll
                for (int e = 0; e < 2; e++) {
                    const float p = __expf(sf[nt][half * 2 + e] - m_new);
                    sf[nt][half * 2 + e] = p;
                    ls += p;
                }
            l_run[half] = l_run[half] * corr + ls;   // lane-partial
            m_run[half] = m_new;
#pragma unroll
            for (int dt = 0; dt < 8; dt++) {
                of[dt][half * 2]     *= corr;
                of[dt][half * 2 + 1] *= corr;
            }
        }

        // ---- O += P V (2 passes: Ph*Vh, Pl*Vh) ----
        const uint32_t vbase = kbase + KTILE_B;
#pragma unroll
        for (int kc = 0; kc < 4; kc++) {
            uint32_t pa_h[4], pa_l[4];
            pa_h[0] = pack_split(sf[kc * 2][0],     sf[kc * 2][1],     pa_l[0]);
            pa_h[1] = pack_split(sf[kc * 2][2],     sf[kc * 2][3],     pa_l[1]);
            pa_h[2] = pack_split(sf[kc * 2 + 1][0], sf[kc * 2 + 1][1], pa_l[2]);
            pa_h[3] = pack_split(sf[kc * 2 + 1][2], sf[kc * 2 + 1][3], pa_l[3]);

            uint32_t vh4[4][4];
#pragma unroll
            for (int dc = 0; dc < 4; dc++) {
                const int krow = kc * 16 + (lg & 1) * 8 + lr;
                const uint32_t sw =
                    SWZ((uint32_t)(krow * 128 + (dc * 16 + (lg >> 1) * 8) * 2));
                ldsm4t(vh4[dc], vbase + sw);
            }
#pragma unroll
            for (int dt = 0; dt < 8; dt++)
                mma16816(of[dt], pa_h, vh4[dt >> 1][(dt & 1) * 2],
                         vh4[dt >> 1][(dt & 1) * 2 + 1]);
#pragma unroll
            for (int dt = 0; dt < 8; dt++)
                mma16816(of[dt], pa_l, vh4[dt >> 1][(dt & 1) * 2],
                         vh4[dt >> 1][(dt & 1) * 2 + 1]);
        }

        if (kb + 1 < nkb) {
            CP_WAIT(0);
            __syncthreads();
        }
    }

    // ---- epilogue: y as single fp16 ----
    float inv[2];
#pragma unroll
    for (int half = 0; half < 2; half++) {
        float l = l_run[half];
        l += __shfl_xor_sync(0xffffffffu, l, 1);
        l += __shfl_xor_sync(0xffffffffu, l, 2);
        inv[half] = 1.0f / l;
    }
    const size_t orow = qrow0 + wid * 16 + (lane >> 2);
    const size_t obase = orow * EMB + hoff + (lane & 3) * 2;
#pragma unroll
    for (int dt = 0; dt < 8; dt++) {
        *(uint32_t*)(Yh + obase + dt * 8) =
            pack_hi(of[dt][0] * inv[0], of[dt][1] * inv[0]);
        *(uint32_t*)(Yh + obase + 8 * EMB + dt * 8) =
            pack_hi(of[dt][2] * inv[1], of[dt][3] * inv[1]);
    }
}

// ---------------------------------------------------------------------------
// Launch
// ---------------------------------------------------------------------------
extern "C" void kernel_launch(void* const* d_in, const int* in_sizes, int n_in,
                              void* d_out, int out_size)
{
    const float* x      = (const float*)d_in[0];
    const float* w_attn = (const float*)d_in[1];
    const float* b_attn = (const float*)d_in[2];
    const float* w_proj = (const float*)d_in[3];
    const float* b_proj = (const float*)d_in[4];
    float* out = (float*)d_out;

    void* p;
    cudaGetSymbolAddress(&p, g_x_h);    __half* x_h   = (__half*)p;
    cudaGetSymbolAddress(&p, g_x_l);    __half* x_l   = (__half*)p;
    cudaGetSymbolAddress(&p, g_wa_h);   __half* wa_h  = (__half*)p;
    cudaGetSymbolAddress(&p, g_wp_h);   __half* wp_h  = (__half*)p;
    cudaGetSymbolAddress(&p, g_qkv_h);  __half* qkv_h = (__half*)p;
    cudaGetSymbolAddress(&p, g_qkv_l);  __half* qkv_l = (__half*)p;
    cudaGetSymbolAddress(&p, g_y_h);    __half* y_h   = (__half*)p;

    cudaFuncSetAttribute(gemm_hmma<true>,
                         cudaFuncAttributeMaxDynamicSharedMemorySize, GSMEM);
    cudaFuncSetAttribute(gemm_hmma<false>,
                         cudaFuncAttributeMaxDynamicSharedMemorySize, GSMEM);
    cudaFuncSetAttribute(attn_hmma,
                         cudaFuncAttributeMaxDynamicSharedMemorySize, ASMEM);

    // 0) splits: x -> hi+lo; weights -> hi only
    {
        int n4 = MTOT * EMB / 4;
        split_kernel<<<n4 / 256, 256>>>((const float4*)x, (uint2*)x_h, (uint2*)x_l, n4);
        n4 = C3 * EMB / 4;
        split_kernel<<<n4 / 256, 256>>>((const float4*)w_attn, (uint2*)wa_h, nullptr, n4);
        n4 = EMB * EMB / 4;
        split_kernel<<<n4 / 256, 256>>>((const float4*)w_proj, (uint2*)wp_h, nullptr, n4);
    }

    // 1) qkv = x @ w_attn^T + b_attn; q columns (n<1024) 2-pass + split out,
    //    k/v columns 1-pass + hi-only out
    {
        dim3 grid(C3 / 128, MTOT / 128);
        gemm_hmma<true><<<grid, 256, GSMEM>>>(x_h, x_l, wa_h, b_attn,
                                              nullptr, qkv_h, qkv_l,
                                              MTOT, C3, EMB, /*n_alo=*/EMB);
    }

    // 2) HMMA flash attention -> fp16 y (hi only)
    {
        dim3 grid(SEQ / 64, HEADS, BATCH);
        attn_hmma<<<grid, 128, ASMEM>>>(qkv_h, qkv_l, y_h);
    }

    // 3) out = y @ w_proj^T + b_proj (1-pass, fp32 out)
    {
        dim3 grid(EMB / 128, MTOT / 128);
        gemm_hmma<false><<<grid, 256, GSMEM>>>(y_h, y_h, wp_h, b_proj,
                                               out, nullptr, nullptr,
                                               MTOT, EMB, EMB, /*n_alo=*/0);
    }
}

// round 12
// speedup vs baseline: 1.8550x; 1.0879x over previous
#include <cuda_runtime.h>
#include <cuda_fp16.h>
#include <cstdint>

// Problem constants
#define BATCH 2
#define SEQ   2048
#define EMB   1024
#define HEADS 16
#define HDIM  64
#define C3    (3 * EMB)
#define MTOT  (BATCH * SEQ)   // 4096

// Scratch (allocation-free rule: __device__ globals), fp16 split operands
__device__ __half g_x_h[MTOT * EMB];
__device__ __half g_x_l[MTOT * EMB];
__device__ __half g_wa_h[C3 * EMB];
__device__ __half g_wp_h[EMB * EMB];
__device__ __half g_qkv_h[MTOT * C3];
__device__ __half g_qkv_l[MTOT * C3];    // lo written/used for q columns only
__device__ __half g_y_h[MTOT * EMB];

// ---------------------------------------------------------------------------
// helpers (plain sm_80-level PTX: valid at compute_103)
// ---------------------------------------------------------------------------
__device__ __forceinline__ uint32_t smem_u32(const void* p) {
    uint32_t a;
    asm("{ .reg .u64 t; cvta.to.shared.u64 t, %1; cvt.u32.u64 %0, t; }"
        : "=r"(a) : "l"(p));
    return a;
}

__device__ __forceinline__ void cpasync16(uint32_t dst, const void* src) {
    asm volatile("cp.async.cg.shared.global [%0], [%1], 16;"
                 :: "r"(dst), "l"(src) : "memory");
}
#define CP_COMMIT() asm volatile("cp.async.commit_group;" ::: "memory")
#define CP_WAIT(n)  asm volatile("cp.async.wait_group %0;" :: "n"(n) : "memory")

__device__ __forceinline__ void ldsm4(uint32_t* r, uint32_t addr) {
    asm volatile("ldmatrix.sync.aligned.m8n8.x4.shared.b16 {%0,%1,%2,%3}, [%4];"
                 : "=r"(r[0]), "=r"(r[1]), "=r"(r[2]), "=r"(r[3]) : "r"(addr));
}
__device__ __forceinline__ void ldsm4t(uint32_t* r, uint32_t addr) {
    asm volatile("ldmatrix.sync.aligned.m8n8.x4.trans.shared.b16 {%0,%1,%2,%3}, [%4];"
                 : "=r"(r[0]), "=r"(r[1]), "=r"(r[2]), "=r"(r[3]) : "r"(addr));
}

__device__ __forceinline__ void mma16816(float* c, const uint32_t* a,
                                         uint32_t b0, uint32_t b1) {
    asm volatile(
        "mma.sync.aligned.m16n8k16.row.col.f32.f16.f16.f32 "
        "{%0,%1,%2,%3}, {%4,%5,%6,%7}, {%8,%9}, {%0,%1,%2,%3};"
        : "+f"(c[0]), "+f"(c[1]), "+f"(c[2]), "+f"(c[3])
        : "r"(a[0]), "r"(a[1]), "r"(a[2]), "r"(a[3]), "r"(b0), "r"(b1));
}

#define SWZ(o) ((o) ^ (((o) >> 3) & 0x70))

// fp32 pair -> packed f16x2 hi (return) + lo residual (out param)
__device__ __forceinline__ uint32_t pack_split(float x, float y, uint32_t& lo) {
    __half2 h = __float22half2_rn(make_float2(x, y));
    const float2 f = __half22float2(h);
    __half2 l = __float22half2_rn(make_float2(x - f.x, y - f.y));
    lo = *(uint32_t*)&l;
    return *(uint32_t*)&h;
}
__device__ __forceinline__ uint32_t pack_hi(float x, float y) {
    __half2 h = __float22half2_rn(make_float2(x, y));
    return *(uint32_t*)&h;
}

// ---------------------------------------------------------------------------
// split fp32 -> hi fp16 (+ optional lo residual)
// ---------------------------------------------------------------------------
__global__ __launch_bounds__(256) void split_kernel(
    const float4* __restrict__ in, uint2* __restrict__ hi,
    uint2* __restrict__ lo, int n4)
{
    const int i = blockIdx.x * 256 + threadIdx.x;
    if (i >= n4) return;
    const float4 v = in[i];
    uint32_t l0, l1;
    const uint32_t h0 = pack_split(v.x, v.y, l0);
    const uint32_t h1 = pack_split(v.z, v.w, l1);
    hi[i] = make_uint2(h0, h1);
    if (lo) lo[i] = make_uint2(l0, l1);
}

// ---------------------------------------------------------------------------
// HMMA NT GEMM, fp16, variable passes: C = (Ah [+ Al if bn<n_alo]) @ Bh^T + bias.
// 256 threads, 8 warps (2x4), warp tile 64x32. CTA 128x128, BK=64.
// 3-stage cp.async ring, one __syncthreads per k-tile.
// SPLIT_OUT: write fp16 hi (Ch) always + lo (Cl) for bn<n_alo; else fp32 C.
// ---------------------------------------------------------------------------
#define TILE_B  16384
#define STAGE_B (3 * TILE_B)            // Ah, Al, Bh slots (Al unused if !alo)
#define GSMEM   (3 * STAGE_B + 1024)

template<bool SPLIT_OUT>
__global__ __launch_bounds__(256, 1) void gemm_hmma(
    const __half* __restrict__ Ah, const __half* __restrict__ Al,
    const __half* __restrict__ Bh,
    const float* __restrict__ bias, float* __restrict__ C,
    __half* __restrict__ Ch, __half* __restrict__ Cl,
    int M, int N, int K, int n_alo)
{
    extern __shared__ char smr[];
    const uint32_t sb = (smem_u32(smr) + 1023u) & ~1023u;

    const int t    = threadIdx.x;
    const int lane = t & 31;
    const int wid  = t >> 5;
    const int warp_m = wid & 1;     // 0..1 (64 rows each)
    const int warp_n = wid >> 1;    // 0..3 (32 cols each)
    const int bm = blockIdx.y * 128;
    const int bn = blockIdx.x * 128;
    const bool alo = bn < n_alo;    // uniform per CTA

    const int lg = lane >> 3, lr = lane & 7;
    const int a_mloc = (lg & 1) * 8 + lr;  const int a_kh = lg >> 1;
    const int b_nloc = (lg >> 1) * 8 + lr; const int b_kh = lg & 1;

    const int NC = K >> 6;

    auto issue = [&](int kt, int stage) {
        const uint32_t base = sb + stage * STAGE_B;
        const int k0 = kt << 6;
#pragma unroll
        for (int l = 0; l < 4; l++) {
            const int idx = t + 256 * l;
            const int row = idx >> 3;
            const int ch  = idx & 7;
            const uint32_t sw = SWZ((uint32_t)(row * 128 + ch * 16));
            const size_t ga = (size_t)(bm + row) * K + k0 + ch * 8;
            const size_t gb = (size_t)(bn + row) * K + k0 + ch * 8;
            cpasync16(base + sw,              Ah + ga);
            if (alo) cpasync16(base + TILE_B + sw, Al + ga);
            cpasync16(base + 2 * TILE_B + sw, Bh + gb);
        }
    };

    float acc[4][4][4];
#pragma unroll
    for (int i = 0; i < 4; i++)
#pragma unroll
        for (int j = 0; j < 4; j++)
#pragma unroll
            for (int e = 0; e < 4; e++) acc[i][j][e] = 0.0f;

    issue(0, 0); CP_COMMIT();
    issue(1, 1); CP_COMMIT();

    int stage = 0;
    for (int kt = 0; kt < NC; kt++) {
        if (kt + 1 < NC) { CP_WAIT(1); } else { CP_WAIT(0); }
        __syncthreads();
        if (kt + 2 < NC) {
            int ns = stage + 2; if (ns >= 3) ns -= 3;
            issue(kt + 2, ns);
            CP_COMMIT();
        }

        const uint32_t base = sb + stage * STAGE_B;
#pragma unroll
        for (int ks = 0; ks < 4; ks++) {
            uint32_t ah[4][4], al[4][4], bh[2][4];
#pragma unroll
            for (int mt = 0; mt < 4; mt++) {
                const int row = warp_m * 64 + mt * 16 + a_mloc;
                const uint32_t sw = SWZ((uint32_t)(row * 128 + ks * 32 + a_kh * 16));
                ldsm4(ah[mt], base + sw);
                if (alo) ldsm4(al[mt], base + TILE_B + sw);
            }
#pragma unroll
            for (int np = 0; np < 2; np++) {
                const int row = warp_n * 32 + np * 16 + b_nloc;
                const uint32_t sw = SWZ((uint32_t)(row * 128 + ks * 32 + b_kh * 16));
                ldsm4(bh[np], base + 2 * TILE_B + sw);
            }
            // pass 1: Ah*Bh
#pragma unroll
            for (int mt = 0; mt < 4; mt++)
#pragma unroll
                for (int nt = 0; nt < 4; nt++)
                    mma16816(acc[mt][nt], ah[mt],
                             bh[nt >> 1][(nt & 1) * 2], bh[nt >> 1][(nt & 1) * 2 + 1]);
            // pass 2: Al*Bh (precision-critical columns only)
            if (alo) {
#pragma unroll
                for (int mt = 0; mt < 4; mt++)
#pragma unroll
                    for (int nt = 0; nt < 4; nt++)
                        mma16816(acc[mt][nt], al[mt],
                                 bh[nt >> 1][(nt & 1) * 2], bh[nt >> 1][(nt & 1) * 2 + 1]);
            }
        }
        if (++stage >= 3) stage = 0;
    }

#pragma unroll
    for (int mt = 0; mt < 4; mt++) {
        const int row = bm + warp_m * 64 + mt * 16 + (lane >> 2);
#pragma unroll
        for (int nt = 0; nt < 4; nt++) {
            const int col = bn + warp_n * 32 + nt * 8 + (lane & 3) * 2;
            const float2 bb = *(const float2*)(bias + col);
            const float c00 = acc[mt][nt][0] + bb.x;
            const float c01 = acc[mt][nt][1] + bb.y;
            const float c10 = acc[mt][nt][2] + bb.x;
            const float c11 = acc[mt][nt][3] + bb.y;
            if (SPLIT_OUT) {
                if (alo) {
                    uint32_t lo0, lo1;
                    const uint32_t hi0 = pack_split(c00, c01, lo0);
                    const uint32_t hi1 = pack_split(c10, c11, lo1);
                    *(uint32_t*)(Ch + (size_t)row * N + col)       = hi0;
                    *(uint32_t*)(Cl + (size_t)row * N + col)       = lo0;
                    *(uint32_t*)(Ch + (size_t)(row + 8) * N + col) = hi1;
                    *(uint32_t*)(Cl + (size_t)(row + 8) * N + col) = lo1;
                } else {
                    *(uint32_t*)(Ch + (size_t)row * N + col)       = pack_hi(c00, c01);
                    *(uint32_t*)(Ch + (size_t)(row + 8) * N + col) = pack_hi(c10, c11);
                }
            } else {
                *(float2*)(C + (size_t)row * N + col)       = make_float2(c00, c01);
                *(float2*)(C + (size_t)(row + 8) * N + col) = make_float2(c10, c11);
            }
        }
    }
}

// ---------------------------------------------------------------------------
// HMMA flash attention: S = (Qh+Ql) Kh^T (2-pass), PV = Ph Vh (1-pass).
// CTA: 64 q-rows x (head, batch), 128 threads (4 warps x 16 rows),
// 3 CTAs/SM (~49KB smem). y written as single fp16 (hi only).
// ---------------------------------------------------------------------------
#define KTILE_B   8192           // 64 rows * 128 B
#define ASTAGE_B  (2 * KTILE_B)  // Kh + Vh = 16 KB
#define ASMEM     (16384 + 2 * ASTAGE_B + 1024)

__global__ __launch_bounds__(128, 3) void attn_hmma(
    const __half* __restrict__ Gh, const __half* __restrict__ Gl,
    __half* __restrict__ Yh)
{
    extern __shared__ char smr[];
    const uint32_t sb  = (smem_u32(smr) + 1023u) & ~1023u;
    const uint32_t sQh = sb;
    const uint32_t sQl = sb + 8192;
    const uint32_t sKV = sb + 16384;

    const int t = threadIdx.x;
    const int lane = t & 31, wid = t >> 5;
    const int lg = lane >> 3, lr = lane & 7;
    const int a_mloc = (lg & 1) * 8 + lr, a_kh = lg >> 1;
    const int b_nloc = (lg >> 1) * 8 + lr, b_kh = lg & 1;

    const int qt = gridDim.x - 1 - blockIdx.x;   // heaviest first
    const int h  = blockIdx.y;
    const int b  = blockIdx.z;

    const size_t qrow0 = (size_t)b * SEQ + qt * 64;
    const size_t hoff  = (size_t)h * HDIM;

    auto fill = [&](int kb, int st) {
        const uint32_t base = sKV + st * ASTAGE_B;
#pragma unroll
        for (int l = 0; l < 4; l++) {
            const int idx = t + 128 * l;
            const int row = idx >> 3, ch = idx & 7;
            const uint32_t sw = SWZ((uint32_t)(row * 128 + ch * 16));
            const size_t g = ((size_t)b * SEQ + kb * 64 + row) * C3 + hoff + ch * 8;
            cpasync16(base + sw,           Gh + g + EMB);       // Kh
            cpasync16(base + KTILE_B + sw, Gh + g + 2 * EMB);   // Vh
        }
    };

    // prologue: Q tiles (hi+lo) + KV block 0 in one group
#pragma unroll
    for (int l = 0; l < 4; l++) {
        const int idx = t + 128 * l;
        const int row = idx >> 3, ch = idx & 7;
        const uint32_t sw = SWZ((uint32_t)(row * 128 + ch * 16));
        const size_t g = (qrow0 + row) * C3 + hoff + ch * 8;
        cpasync16(sQh + sw, Gh + g);
        cpasync16(sQl + sw, Gl + g);
    }
    fill(0, 0);
    CP_COMMIT();
    CP_WAIT(0);
    __syncthreads();

    // Q fragments (registers, whole CTA lifetime)
    uint32_t qh[4][4], ql[4][4];
#pragma unroll
    for (int ks = 0; ks < 4; ks++) {
        const int row = wid * 16 + a_mloc;
        const uint32_t sw = SWZ((uint32_t)(row * 128 + ks * 32 + a_kh * 16));
        ldsm4(qh[ks], sQh + sw);
        ldsm4(ql[ks], sQl + sw);
    }

    float of[8][4];
#pragma unroll
    for (int i = 0; i < 8; i++)
#pragma unroll
        for (int e = 0; e < 4; e++) of[i][e] = 0.0f;
    float m_run[2] = {-1e30f, -1e30f};
    float l_run[2] = {0.0f, 0.0f};

    const int nkb = qt + 1;
    for (int kb = 0; kb < nkb; kb++) {
        if (kb + 1 < nkb) {
            fill(kb + 1, (kb + 1) & 1);
            CP_COMMIT();
        }

        const uint32_t kbase = sKV + (kb & 1) * ASTAGE_B;

        // ---- S = Q K^T (2 passes: Qh*Kh, Ql*Kh) ----
        float sf[8][4];
#pragma unroll
        for (int i = 0; i < 8; i++)
#pragma unroll
            for (int e = 0; e < 4; e++) sf[i][e] = 0.0f;

#pragma unroll
        for (int ks = 0; ks < 4; ks++) {
            uint32_t kh4[4][4];
#pragma unroll
            for (int g = 0; g < 4; g++) {
                const int row = g * 16 + b_nloc;
                const uint32_t sw = SWZ((uint32_t)(row * 128 + ks * 32 + b_kh * 16));
                ldsm4(kh4[g], kbase + sw);
            }
#pragma unroll
            for (int nt = 0; nt < 8; nt++)
                mma16816(sf[nt], qh[ks], kh4[nt >> 1][(nt & 1) * 2],
                         kh4[nt >> 1][(nt & 1) * 2 + 1]);
#pragma unroll
            for (int nt = 0; nt < 8; nt++)
                mma16816(sf[nt], ql[ks], kh4[nt >> 1][(nt & 1) * 2],
                         kh4[nt >> 1][(nt & 1) * 2 + 1]);
        }

        // ---- online softmax ----
        const bool diag = (kb == qt);
#pragma unroll
        for (int half = 0; half < 2; half++) {
            const int rowg = qt * 64 + wid * 16 + (lane >> 2) + half * 8;
            float mx = -1e30f;
#pragma unroll
            for (int nt = 0; nt < 8; nt++)
#pragma unroll
                for (int e = 0; e < 2; e++) {
                    float v = sf[nt][half * 2 + e] * 0.125f;
                    if (diag) {
                        const int colg = kb * 64 + nt * 8 + (lane & 3) * 2 + e;
                        if (colg > rowg) v = -1e30f;
                    }
                    sf[nt][half * 2 + e] = v;
                    mx = fmaxf(mx, v);
                }
            mx = fmaxf(mx, __shfl_xor_sync(0xffffffffu, mx, 1));
            mx = fmaxf(mx, __shfl_xor_sync(0xffffffffu, mx, 2));
            const float m_new = fmaxf(m_run[half], mx);
            const float corr  = __expf(m_run[half] - m_new);
            float ls = 0.0f;
#pragma unroll
            for (int nt = 0; nt < 8; nt++)
#pragma unroll
                for (int e = 0; e < 2; e++) {
                    const float p = __expf(sf[nt][half * 2 + e] - m_new);
                    sf[nt][half * 2 + e] = p;
                    ls += p;
                }
            l_run[half] = l_run[half] * corr + ls;   // lane-partial
            m_run[half] = m_new;
#pragma unroll
            for (int dt = 0; dt < 8; dt++) {
                of[dt][half * 2]     *= corr;
                of[dt][half * 2 + 1] *= corr;
            }
        }

        // ---- O += P V (1 pass: Ph*Vh) ----
        const uint32_t vbase = kbase + KTILE_B;
#pragma unroll
        for (int kc = 0; kc < 4; kc++) {
            uint32_t pa_h[4];
            pa_h[0] = pack_hi(sf[kc * 2][0],     sf[kc * 2][1]);
            pa_h[1] = pack_hi(sf[kc * 2][2],     sf[kc * 2][3]);
            pa_h[2] = pack_hi(sf[kc * 2 + 1][0], sf[kc * 2 + 1][1]);
            pa_h[3] = pack_hi(sf[kc * 2 + 1][2], sf[kc * 2 + 1][3]);

            uint32_t vh4[4][4];
#pragma unroll
            for (int dc = 0; dc < 4; dc++) {
                const int krow = kc * 16 + (lg & 1) * 8 + lr;
                const uint32_t sw =
                    SWZ((uint32_t)(krow * 128 + (dc * 16 + (lg >> 1) * 8) * 2));
                ldsm4t(vh4[dc], vbase + sw);
            }
#pragma unroll
            for (int dt = 0; dt < 8; dt++)
                mma16816(of[dt], pa_h, vh4[dt >> 1][(dt & 1) * 2],
                         vh4[dt >> 1][(dt & 1) * 2 + 1]);
        }

        if (kb + 1 < nkb) {
            CP_WAIT(0);
            __syncthreads();
        }
    }

    // ---- epilogue: y as single fp16 ----
    float inv[2];
#pragma unroll
    for (int half = 0; half < 2; half++) {
        float l = l_run[half];
        l += __shfl_xor_sync(0xffffffffu, l, 1);
        l += __shfl_xor_sync(0xffffffffu, l, 2);
        inv[half] = 1.0f / l;
    }
    const size_t orow = qrow0 + wid * 16 + (lane >> 2);
    const size_t obase = orow * EMB + hoff + (lane & 3) * 2;
#pragma unroll
    for (int dt = 0; dt < 8; dt++) {
        *(uint32_t*)(Yh + obase + dt * 8) =
            pack_hi(of[dt][0] * inv[0], of[dt][1] * inv[0]);
        *(uint32_t*)(Yh + obase + 8 * EMB + dt * 8) =
            pack_hi(of[dt][2] * inv[1], of[dt][3] * inv[1]);
    }
}

// ---------------------------------------------------------------------------
// Launch
// ---------------------------------------------------------------------------
extern "C" void kernel_launch(void* const* d_in, const int* in_sizes, int n_in,
                              void* d_out, int out_size)
{
    const float* x      = (const float*)d_in[0];
    const float* w_attn = (const float*)d_in[1];
    const float* b_attn = (const float*)d_in[2];
    const float* w_proj = (const float*)d_in[3];
    const float* b_proj = (const float*)d_in[4];
    float* out = (float*)d_out;

    void* p;
    cudaGetSymbolAddress(&p, g_x_h);    __half* x_h   = (__half*)p;
    cudaGetSymbolAddress(&p, g_x_l);    __half* x_l   = (__half*)p;
    cudaGetSymbolAddress(&p, g_wa_h);   __half* wa_h  = (__half*)p;
    cudaGetSymbolAddress(&p, g_wp_h);   __half* wp_h  = (__half*)p;
    cudaGetSymbolAddress(&p, g_qkv_h);  __half* qkv_h = (__half*)p;
    cudaGetSymbolAddress(&p, g_qkv_l);  __half* qkv_l = (__half*)p;
    cudaGetSymbolAddress(&p, g_y_h);    __half* y_h   = (__half*)p;

    cudaFuncSetAttribute(gemm_hmma<true>,
                         cudaFuncAttributeMaxDynamicSharedMemorySize, GSMEM);
    cudaFuncSetAttribute(gemm_hmma<false>,
                         cudaFuncAttributeMaxDynamicSharedMemorySize, GSMEM);
    cudaFuncSetAttribute(attn_hmma,
                         cudaFuncAttributeMaxDynamicSharedMemorySize, ASMEM);

    // 0) splits: x -> hi+lo; weights -> hi only
    {
        int n4 = MTOT * EMB / 4;
        split_kernel<<<n4 / 256, 256>>>((const float4*)x, (uint2*)x_h, (uint2*)x_l, n4);
        n4 = C3 * EMB / 4;
        split_kernel<<<n4 / 256, 256>>>((const float4*)w_attn, (uint2*)wa_h, nullptr, n4);
        n4 = EMB * EMB / 4;
        split_kernel<<<n4 / 256, 256>>>((const float4*)w_proj, (uint2*)wp_h, nullptr, n4);
    }

    // 1) qkv = x @ w_attn^T + b_attn; q columns (n<1024) 2-pass + split out,
    //    k/v columns 1-pass + hi-only out
    {
        dim3 grid(C3 / 128, MTOT / 128);
        gemm_hmma<true><<<grid, 256, GSMEM>>>(x_h, x_l, wa_h, b_attn,
                                              nullptr, qkv_h, qkv_l,
                                              MTOT, C3, EMB, /*n_alo=*/EMB);
    }

    // 2) HMMA flash attention -> fp16 y (hi only)
    {
        dim3 grid(SEQ / 64, HEADS, BATCH);
        attn_hmma<<<grid, 128, ASMEM>>>(qkv_h, qkv_l, y_h);
    }

    // 3) out = y @ w_proj^T + b_proj (1-pass, fp32 out)
    {
        dim3 grid(EMB / 128, MTOT / 128);
        gemm_hmma<false><<<grid, 256, GSMEM>>>(y_h, y_h, wp_h, b_proj,
                                               out, nullptr, nullptr,
                                               MTOT, EMB, EMB, /*n_alo=*/0);
    }
}

// round 13
// speedup vs baseline: 2.2282x; 1.2012x over previous
#include <cuda_runtime.h>
#include <cuda_fp16.h>
#include <cstdint>

// Problem constants
#define BATCH 2
#define SEQ   2048
#define EMB   1024
#define HEADS 16
#define HDIM  64
#define C3    (3 * EMB)
#define MTOT  (BATCH * SEQ)   // 4096

// Scratch (allocation-free rule: __device__ globals), fp16 operands
__device__ __half g_x_h[MTOT * EMB];
__device__ __half g_wa_h[C3 * EMB];
__device__ __half g_wp_h[EMB * EMB];
__device__ __half g_qkv_h[MTOT * C3];
__device__ __half g_y_h[MTOT * EMB];

// ---------------------------------------------------------------------------
// helpers (plain sm_80-level PTX: valid at compute_103)
// ---------------------------------------------------------------------------
__device__ __forceinline__ uint32_t smem_u32(const void* p) {
    uint32_t a;
    asm("{ .reg .u64 t; cvta.to.shared.u64 t, %1; cvt.u32.u64 %0, t; }"
        : "=r"(a) : "l"(p));
    return a;
}

__device__ __forceinline__ void cpasync16(uint32_t dst, const void* src) {
    asm volatile("cp.async.cg.shared.global [%0], [%1], 16;"
                 :: "r"(dst), "l"(src) : "memory");
}
#define CP_COMMIT() asm volatile("cp.async.commit_group;" ::: "memory")
#define CP_WAIT(n)  asm volatile("cp.async.wait_group %0;" :: "n"(n) : "memory")

__device__ __forceinline__ void ldsm4(uint32_t* r, uint32_t addr) {
    asm volatile("ldmatrix.sync.aligned.m8n8.x4.shared.b16 {%0,%1,%2,%3}, [%4];"
                 : "=r"(r[0]), "=r"(r[1]), "=r"(r[2]), "=r"(r[3]) : "r"(addr));
}
__device__ __forceinline__ void ldsm4t(uint32_t* r, uint32_t addr) {
    asm volatile("ldmatrix.sync.aligned.m8n8.x4.trans.shared.b16 {%0,%1,%2,%3}, [%4];"
                 : "=r"(r[0]), "=r"(r[1]), "=r"(r[2]), "=r"(r[3]) : "r"(addr));
}

__device__ __forceinline__ void mma16816(float* c, const uint32_t* a,
                                         uint32_t b0, uint32_t b1) {
    asm volatile(
        "mma.sync.aligned.m16n8k16.row.col.f32.f16.f16.f32 "
        "{%0,%1,%2,%3}, {%4,%5,%6,%7}, {%8,%9}, {%0,%1,%2,%3};"
        : "+f"(c[0]), "+f"(c[1]), "+f"(c[2]), "+f"(c[3])
        : "r"(a[0]), "r"(a[1]), "r"(a[2]), "r"(a[3]), "r"(b0), "r"(b1));
}

#define SWZ(o) ((o) ^ (((o) >> 3) & 0x70))

__device__ __forceinline__ uint32_t pack_hi(float x, float y) {
    __half2 h = __float22half2_rn(make_float2(x, y));
    return *(uint32_t*)&h;
}

// ---------------------------------------------------------------------------
// convert fp32 -> fp16
// ---------------------------------------------------------------------------
__global__ __launch_bounds__(256) void split_kernel(
    const float4* __restrict__ in, uint2* __restrict__ hi, int n4)
{
    const int i = blockIdx.x * 256 + threadIdx.x;
    if (i >= n4) return;
    const float4 v = in[i];
    hi[i] = make_uint2(pack_hi(v.x, v.y), pack_hi(v.z, v.w));
}

// ---------------------------------------------------------------------------
// HMMA NT GEMM, fp16 single-pass: C = Ah @ Bh^T + bias.
// 256 threads, 8 warps (2x4), warp tile 64x32. CTA 128x128, BK=64.
// 3-stage cp.async ring (32 KB/stage), one __syncthreads per k-tile.
// OUT_FP16: write fp16 C; else fp32 C.
// ---------------------------------------------------------------------------
#define TILE_B  16384
#define STAGE_B (2 * TILE_B)            // Ah, Bh
#define GSMEM   (3 * STAGE_B + 1024)

template<bool OUT_FP16>
__global__ __launch_bounds__(256, 1) void gemm_hmma(
    const __half* __restrict__ Ah, const __half* __restrict__ Bh,
    const float* __restrict__ bias, float* __restrict__ C,
    __half* __restrict__ Ch,
    int M, int N, int K)
{
    extern __shared__ char smr[];
    const uint32_t sb = (smem_u32(smr) + 1023u) & ~1023u;

    const int t    = threadIdx.x;
    const int lane = t & 31;
    const int wid  = t >> 5;
    const int warp_m = wid & 1;     // 0..1 (64 rows each)
    const int warp_n = wid >> 1;    // 0..3 (32 cols each)
    const int bm = blockIdx.y * 128;
    const int bn = blockIdx.x * 128;

    const int lg = lane >> 3, lr = lane & 7;
    const int a_mloc = (lg & 1) * 8 + lr;  const int a_kh = lg >> 1;
    const int b_nloc = (lg >> 1) * 8 + lr; const int b_kh = lg & 1;

    const int NC = K >> 6;

    auto issue = [&](int kt, int stage) {
        const uint32_t base = sb + stage * STAGE_B;
        const int k0 = kt << 6;
#pragma unroll
        for (int l = 0; l < 4; l++) {
            const int idx = t + 256 * l;
            const int row = idx >> 3;
            const int ch  = idx & 7;
            const uint32_t sw = SWZ((uint32_t)(row * 128 + ch * 16));
            const size_t ga = (size_t)(bm + row) * K + k0 + ch * 8;
            const size_t gb = (size_t)(bn + row) * K + k0 + ch * 8;
            cpasync16(base + sw,          Ah + ga);
            cpasync16(base + TILE_B + sw, Bh + gb);
        }
    };

    float acc[4][4][4];
#pragma unroll
    for (int i = 0; i < 4; i++)
#pragma unroll
        for (int j = 0; j < 4; j++)
#pragma unroll
            for (int e = 0; e < 4; e++) acc[i][j][e] = 0.0f;

    issue(0, 0); CP_COMMIT();
    issue(1, 1); CP_COMMIT();

    int stage = 0;
    for (int kt = 0; kt < NC; kt++) {
        if (kt + 1 < NC) { CP_WAIT(1); } else { CP_WAIT(0); }
        __syncthreads();
        if (kt + 2 < NC) {
            int ns = stage + 2; if (ns >= 3) ns -= 3;
            issue(kt + 2, ns);
            CP_COMMIT();
        }

        const uint32_t base = sb + stage * STAGE_B;
#pragma unroll
        for (int ks = 0; ks < 4; ks++) {
            uint32_t ah[4][4], bh[2][4];
#pragma unroll
            for (int mt = 0; mt < 4; mt++) {
                const int row = warp_m * 64 + mt * 16 + a_mloc;
                const uint32_t sw = SWZ((uint32_t)(row * 128 + ks * 32 + a_kh * 16));
                ldsm4(ah[mt], base + sw);
            }
#pragma unroll
            for (int np = 0; np < 2; np++) {
                const int row = warp_n * 32 + np * 16 + b_nloc;
                const uint32_t sw = SWZ((uint32_t)(row * 128 + ks * 32 + b_kh * 16));
                ldsm4(bh[np], base + TILE_B + sw);
            }
#pragma unroll
            for (int mt = 0; mt < 4; mt++)
#pragma unroll
                for (int nt = 0; nt < 4; nt++)
                    mma16816(acc[mt][nt], ah[mt],
                             bh[nt >> 1][(nt & 1) * 2], bh[nt >> 1][(nt & 1) * 2 + 1]);
        }
        if (++stage >= 3) stage = 0;
    }

#pragma unroll
    for (int mt = 0; mt < 4; mt++) {
        const int row = bm + warp_m * 64 + mt * 16 + (lane >> 2);
#pragma unroll
        for (int nt = 0; nt < 4; nt++) {
            const int col = bn + warp_n * 32 + nt * 8 + (lane & 3) * 2;
            const float2 bb = *(const float2*)(bias + col);
            const float c00 = acc[mt][nt][0] + bb.x;
            const float c01 = acc[mt][nt][1] + bb.y;
            const float c10 = acc[mt][nt][2] + bb.x;
            const float c11 = acc[mt][nt][3] + bb.y;
            if (OUT_FP16) {
                *(uint32_t*)(Ch + (size_t)row * N + col)       = pack_hi(c00, c01);
                *(uint32_t*)(Ch + (size_t)(row + 8) * N + col) = pack_hi(c10, c11);
            } else {
                *(float2*)(C + (size_t)row * N + col)       = make_float2(c00, c01);
                *(float2*)(C + (size_t)(row + 8) * N + col) = make_float2(c10, c11);
            }
        }
    }
}

// ---------------------------------------------------------------------------
// HMMA flash attention, fully fp16 single-pass: S = Qh Kh^T, O += Ph Vh.
// CTA: 64 q-rows x (head, batch), 128 threads (4 warps x 16 rows),
// 3 CTAs/SM (~42KB smem). y written as fp16.
// ---------------------------------------------------------------------------
#define KTILE_B   8192           // 64 rows * 128 B
#define ASTAGE_B  (2 * KTILE_B)  // Kh + Vh = 16 KB
#define ASMEM     (8192 + 2 * ASTAGE_B + 1024)

__global__ __launch_bounds__(128, 3) void attn_hmma(
    const __half* __restrict__ Gh, __half* __restrict__ Yh)
{
    extern __shared__ char smr[];
    const uint32_t sb  = (smem_u32(smr) + 1023u) & ~1023u;
    const uint32_t sQh = sb;
    const uint32_t sKV = sb + 8192;

    const int t = threadIdx.x;
    const int lane = t & 31, wid = t >> 5;
    const int lg = lane >> 3, lr = lane & 7;
    const int a_mloc = (lg & 1) * 8 + lr, a_kh = lg >> 1;
    const int b_nloc = (lg >> 1) * 8 + lr, b_kh = lg & 1;

    const int qt = gridDim.x - 1 - blockIdx.x;   // heaviest first
    const int h  = blockIdx.y;
    const int b  = blockIdx.z;

    const size_t qrow0 = (size_t)b * SEQ + qt * 64;
    const size_t hoff  = (size_t)h * HDIM;

    auto fill = [&](int kb, int st) {
        const uint32_t base = sKV + st * ASTAGE_B;
#pragma unroll
        for (int l = 0; l < 4; l++) {
            const int idx = t + 128 * l;
            const int row = idx >> 3, ch = idx & 7;
            const uint32_t sw = SWZ((uint32_t)(row * 128 + ch * 16));
            const size_t g = ((size_t)b * SEQ + kb * 64 + row) * C3 + hoff + ch * 8;
            cpasync16(base + sw,           Gh + g + EMB);       // Kh
            cpasync16(base + KTILE_B + sw, Gh + g + 2 * EMB);   // Vh
        }
    };

    // prologue: Q tile + KV block 0 in one group
#pragma unroll
    for (int l = 0; l < 4; l++) {
        const int idx = t + 128 * l;
        const int row = idx >> 3, ch = idx & 7;
        const uint32_t sw = SWZ((uint32_t)(row * 128 + ch * 16));
        const size_t g = (qrow0 + row) * C3 + hoff + ch * 8;
        cpasync16(sQh + sw, Gh + g);
    }
    fill(0, 0);
    CP_COMMIT();
    CP_WAIT(0);
    __syncthreads();

    // Q fragments (registers, whole CTA lifetime)
    uint32_t qh[4][4];
#pragma unroll
    for (int ks = 0; ks < 4; ks++) {
        const int row = wid * 16 + a_mloc;
        const uint32_t sw = SWZ((uint32_t)(row * 128 + ks * 32 + a_kh * 16));
        ldsm4(qh[ks], sQh + sw);
    }

    float of[8][4];
#pragma unroll
    for (int i = 0; i < 8; i++)
#pragma unroll
        for (int e = 0; e < 4; e++) of[i][e] = 0.0f;
    float m_run[2] = {-1e30f, -1e30f};
    float l_run[2] = {0.0f, 0.0f};

    const int nkb = qt + 1;
    for (int kb = 0; kb < nkb; kb++) {
        if (kb + 1 < nkb) {
            fill(kb + 1, (kb + 1) & 1);
            CP_COMMIT();
        }

        const uint32_t kbase = sKV + (kb & 1) * ASTAGE_B;

        // ---- S = Qh Kh^T (1 pass) ----
        float sf[8][4];
#pragma unroll
        for (int i = 0; i < 8; i++)
#pragma unroll
            for (int e = 0; e < 4; e++) sf[i][e] = 0.0f;

#pragma unroll
        for (int ks = 0; ks < 4; ks++) {
            uint32_t kh4[4][4];
#pragma unroll
            for (int g = 0; g < 4; g++) {
                const int row = g * 16 + b_nloc;
                const uint32_t sw = SWZ((uint32_t)(row * 128 + ks * 32 + b_kh * 16));
                ldsm4(kh4[g], kbase + sw);
            }
#pragma unroll
            for (int nt = 0; nt < 8; nt++)
                mma16816(sf[nt], qh[ks], kh4[nt >> 1][(nt & 1) * 2],
                         kh4[nt >> 1][(nt & 1) * 2 + 1]);
        }

        // ---- online softmax ----
        const bool diag = (kb == qt);
#pragma unroll
        for (int half = 0; half < 2; half++) {
            const int rowg = qt * 64 + wid * 16 + (lane >> 2) + half * 8;
            float mx = -1e30f;
#pragma unroll
            for (int nt = 0; nt < 8; nt++)
#pragma unroll
                for (int e = 0; e < 2; e++) {
                    float v = sf[nt][half * 2 + e] * 0.125f;
                    if (diag) {
                        const int colg = kb * 64 + nt * 8 + (lane & 3) * 2 + e;
                        if (colg > rowg) v = -1e30f;
                    }
                    sf[nt][half * 2 + e] = v;
                    mx = fmaxf(mx, v);
                }
            mx = fmaxf(mx, __shfl_xor_sync(0xffffffffu, mx, 1));
            mx = fmaxf(mx, __shfl_xor_sync(0xffffffffu, mx, 2));
            const float m_new = fmaxf(m_run[half], mx);
            const float corr  = __expf(m_run[half] - m_new);
            float ls = 0.0f;
#pragma unroll
            for (int nt = 0; nt < 8; nt++)
#pragma unroll
                for (int e = 0; e < 2; e++) {
                    const float p = __expf(sf[nt][half * 2 + e] - m_new);
                    sf[nt][half * 2 + e] = p;
                    ls += p;
                }
            l_run[half] = l_run[half] * corr + ls;   // lane-partial
            m_run[half] = m_new;
#pragma unroll
            for (int dt = 0; dt < 8; dt++) {
                of[dt][half * 2]     *= corr;
                of[dt][half * 2 + 1] *= corr;
            }
        }

        // ---- O += Ph Vh (1 pass) ----
        const uint32_t vbase = kbase + KTILE_B;
#pragma unroll
        for (int kc = 0; kc < 4; kc++) {
            uint32_t pa_h[4];
            pa_h[0] = pack_hi(sf[kc * 2][0],     sf[kc * 2][1]);
            pa_h[1] = pack_hi(sf[kc * 2][2],     sf[kc * 2][3]);
            pa_h[2] = pack_hi(sf[kc * 2 + 1][0], sf[kc * 2 + 1][1]);
            pa_h[3] = pack_hi(sf[kc * 2 + 1][2], sf[kc * 2 + 1][3]);

            uint32_t vh4[4][4];
#pragma unroll
            for (int dc = 0; dc < 4; dc++) {
                const int krow = kc * 16 + (lg & 1) * 8 + lr;
                const uint32_t sw =
                    SWZ((uint32_t)(krow * 128 + (dc * 16 + (lg >> 1) * 8) * 2));
                ldsm4t(vh4[dc], vbase + sw);
            }
#pragma unroll
            for (int dt = 0; dt < 8; dt++)
                mma16816(of[dt], pa_h, vh4[dt >> 1][(dt & 1) * 2],
                         vh4[dt >> 1][(dt & 1) * 2 + 1]);
        }

        if (kb + 1 < nkb) {
            CP_WAIT(0);
            __syncthreads();
        }
    }

    // ---- epilogue: y as fp16 ----
    float inv[2];
#pragma unroll
    for (int half = 0; half < 2; half++) {
        float l = l_run[half];
        l += __shfl_xor_sync(0xffffffffu, l, 1);
        l += __shfl_xor_sync(0xffffffffu, l, 2);
        inv[half] = 1.0f / l;
    }
    const size_t orow = qrow0 + wid * 16 + (lane >> 2);
    const size_t obase = orow * EMB + hoff + (lane & 3) * 2;
#pragma unroll
    for (int dt = 0; dt < 8; dt++) {
        *(uint32_t*)(Yh + obase + dt * 8) =
            pack_hi(of[dt][0] * inv[0], of[dt][1] * inv[0]);
        *(uint32_t*)(Yh + obase + 8 * EMB + dt * 8) =
            pack_hi(of[dt][2] * inv[1], of[dt][3] * inv[1]);
    }
}

// ---------------------------------------------------------------------------
// Launch
// ---------------------------------------------------------------------------
extern "C" void kernel_launch(void* const* d_in, const int* in_sizes, int n_in,
                              void* d_out, int out_size)
{
    const float* x      = (const float*)d_in[0];
    const float* w_attn = (const float*)d_in[1];
    const float* b_attn = (const float*)d_in[2];
    const float* w_proj = (const float*)d_in[3];
    const float* b_proj = (const float*)d_in[4];
    float* out = (float*)d_out;

    void* p;
    cudaGetSymbolAddress(&p, g_x_h);    __half* x_h   = (__half*)p;
    cudaGetSymbolAddress(&p, g_wa_h);   __half* wa_h  = (__half*)p;
    cudaGetSymbolAddress(&p, g_wp_h);   __half* wp_h  = (__half*)p;
    cudaGetSymbolAddress(&p, g_qkv_h);  __half* qkv_h = (__half*)p;
    cudaGetSymbolAddress(&p, g_y_h);    __half* y_h   = (__half*)p;

    cudaFuncSetAttribute(gemm_hmma<true>,
                         cudaFuncAttributeMaxDynamicSharedMemorySize, GSMEM);
    cudaFuncSetAttribute(gemm_hmma<false>,
                         cudaFuncAttributeMaxDynamicSharedMemorySize, GSMEM);
    cudaFuncSetAttribute(attn_hmma,
                         cudaFuncAttributeMaxDynamicSharedMemorySize, ASMEM);

    // 0) fp32 -> fp16 conversions
    {
        int n4 = MTOT * EMB / 4;
        split_kernel<<<n4 / 256, 256>>>((const float4*)x, (uint2*)x_h, n4);
        n4 = C3 * EMB / 4;
        split_kernel<<<n4 / 256, 256>>>((const float4*)w_attn, (uint2*)wa_h, n4);
        n4 = EMB * EMB / 4;
        split_kernel<<<n4 / 256, 256>>>((const float4*)w_proj, (uint2*)wp_h, n4);
    }

    // 1) qkv = x @ w_attn^T + b_attn (fp16 out)
    {
        dim3 grid(C3 / 128, MTOT / 128);
        gemm_hmma<true><<<grid, 256, GSMEM>>>(x_h, wa_h, b_attn,
                                              nullptr, qkv_h, MTOT, C3, EMB);
    }

    // 2) HMMA flash attention -> fp16 y
    {
        dim3 grid(SEQ / 64, HEADS, BATCH);
        attn_hmma<<<grid, 128, ASMEM>>>(qkv_h, y_h);
    }

    // 3) out = y @ w_proj^T + b_proj (fp32 out)
    {
        dim3 grid(EMB / 128, MTOT / 128);
        gemm_hmma<false><<<grid, 256, GSMEM>>>(y_h, wp_h, b_proj,
                                               out, nullptr, MTOT, EMB, EMB);
    }
}

// round 14
// speedup vs baseline: 2.4861x; 1.1158x over previous
#include <cuda_runtime.h>
#include <cuda_fp16.h>
#include <cstdint>

// Problem constants
#define BATCH 2
#define SEQ   2048
#define EMB   1024
#define HEADS 16
#define HDIM  64
#define C3    (3 * EMB)
#define MTOT  (BATCH * SEQ)   // 4096

// Scratch (allocation-free rule: __device__ globals), fp16 operands
__device__ __half g_x_h[MTOT * EMB];
__device__ __half g_wa_h[C3 * EMB];
__device__ __half g_wp_h[EMB * EMB];
__device__ __half g_qkv_h[MTOT * C3];
__device__ __half g_y_h[MTOT * EMB];

// ---------------------------------------------------------------------------
// helpers (plain sm_80-level PTX: valid at compute_103)
// ---------------------------------------------------------------------------
__device__ __forceinline__ uint32_t smem_u32(const void* p) {
    uint32_t a;
    asm("{ .reg .u64 t; cvta.to.shared.u64 t, %1; cvt.u32.u64 %0, t; }"
        : "=r"(a) : "l"(p));
    return a;
}

__device__ __forceinline__ void cpasync16(uint32_t dst, const void* src) {
    asm volatile("cp.async.cg.shared.global [%0], [%1], 16;"
                 :: "r"(dst), "l"(src) : "memory");
}
#define CP_COMMIT() asm volatile("cp.async.commit_group;" ::: "memory")
#define CP_WAIT(n)  asm volatile("cp.async.wait_group %0;" :: "n"(n) : "memory")

__device__ __forceinline__ void ldsm4(uint32_t* r, uint32_t addr) {
    asm volatile("ldmatrix.sync.aligned.m8n8.x4.shared.b16 {%0,%1,%2,%3}, [%4];"
                 : "=r"(r[0]), "=r"(r[1]), "=r"(r[2]), "=r"(r[3]) : "r"(addr));
}
__device__ __forceinline__ void ldsm4t(uint32_t* r, uint32_t addr) {
    asm volatile("ldmatrix.sync.aligned.m8n8.x4.trans.shared.b16 {%0,%1,%2,%3}, [%4];"
                 : "=r"(r[0]), "=r"(r[1]), "=r"(r[2]), "=r"(r[3]) : "r"(addr));
}

__device__ __forceinline__ void mma16816(float* c, const uint32_t* a,
                                         uint32_t b0, uint32_t b1) {
    asm volatile(
        "mma.sync.aligned.m16n8k16.row.col.f32.f16.f16.f32 "
        "{%0,%1,%2,%3}, {%4,%5,%6,%7}, {%8,%9}, {%0,%1,%2,%3};"
        : "+f"(c[0]), "+f"(c[1]), "+f"(c[2]), "+f"(c[3])
        : "r"(a[0]), "r"(a[1]), "r"(a[2]), "r"(a[3]), "r"(b0), "r"(b1));
}

#define SWZ(o) ((o) ^ (((o) >> 3) & 0x70))

__device__ __forceinline__ uint32_t pack_hi(float x, float y) {
    __half2 h = __float22half2_rn(make_float2(x, y));
    return *(uint32_t*)&h;
}

// ---------------------------------------------------------------------------
// convert fp32 -> fp16
// ---------------------------------------------------------------------------
__global__ __launch_bounds__(256) void split_kernel(
    const float4* __restrict__ in, uint2* __restrict__ hi, int n4)
{
    const int i = blockIdx.x * 256 + threadIdx.x;
    if (i >= n4) return;
    const float4 v = in[i];
    hi[i] = make_uint2(pack_hi(v.x, v.y), pack_hi(v.z, v.w));
}

// ---------------------------------------------------------------------------
// HMMA NT GEMM, fp16 single-pass: C = Ah @ Bh^T + bias.
// 256 threads, 8 warps (2x4), warp tile 64x32. CTA 128x128, BK=64.
// 2-stage cp.async ring (32 KB/stage) -> 66 KB smem -> 2 CTAs/SM.
// Race-free single-sync order: wait(0) -> sync -> issue(kt+1) -> compute(kt).
// OUT_FP16: write fp16 C; else fp32 C.
// ---------------------------------------------------------------------------
#define TILE_B  16384
#define STAGE_B (2 * TILE_B)            // Ah, Bh
#define GSMEM   (2 * STAGE_B + 1024)    // 66.5 KB

template<bool OUT_FP16>
__global__ __launch_bounds__(256, 2) void gemm_hmma(
    const __half* __restrict__ Ah, const __half* __restrict__ Bh,
    const float* __restrict__ bias, float* __restrict__ C,
    __half* __restrict__ Ch,
    int M, int N, int K)
{
    extern __shared__ char smr[];
    const uint32_t sb = (smem_u32(smr) + 1023u) & ~1023u;

    const int t    = threadIdx.x;
    const int lane = t & 31;
    const int wid  = t >> 5;
    const int warp_m = wid & 1;     // 0..1 (64 rows each)
    const int warp_n = wid >> 1;    // 0..3 (32 cols each)
    const int bm = blockIdx.y * 128;
    const int bn = blockIdx.x * 128;

    const int lg = lane >> 3, lr = lane & 7;
    const int a_mloc = (lg & 1) * 8 + lr;  const int a_kh = lg >> 1;
    const int b_nloc = (lg >> 1) * 8 + lr; const int b_kh = lg & 1;

    const int NC = K >> 6;

    auto issue = [&](int kt, int stage) {
        const uint32_t base = sb + stage * STAGE_B;
        const int k0 = kt << 6;
#pragma unroll
        for (int l = 0; l < 4; l++) {
            const int idx = t + 256 * l;
            const int row = idx >> 3;
            const int ch  = idx & 7;
            const uint32_t sw = SWZ((uint32_t)(row * 128 + ch * 16));
            const size_t ga = (size_t)(bm + row) * K + k0 + ch * 8;
            const size_t gb = (size_t)(bn + row) * K + k0 + ch * 8;
            cpasync16(base + sw,          Ah + ga);
            cpasync16(base + TILE_B + sw, Bh + gb);
        }
    };

    float acc[4][4][4];
#pragma unroll
    for (int i = 0; i < 4; i++)
#pragma unroll
        for (int j = 0; j < 4; j++)
#pragma unroll
            for (int e = 0; e < 4; e++) acc[i][j][e] = 0.0f;

    issue(0, 0); CP_COMMIT();

    for (int kt = 0; kt < NC; kt++) {
        CP_WAIT(0);            // group kt is the only outstanding one
        __syncthreads();       // all warps past compute(kt-1); stage safe
        if (kt + 1 < NC) {
            issue(kt + 1, (kt + 1) & 1);   // overlaps compute(kt)
            CP_COMMIT();
        }

        const uint32_t base = sb + (kt & 1) * STAGE_B;
#pragma unroll
        for (int ks = 0; ks < 4; ks++) {
            uint32_t ah[4][4], bh[2][4];
#pragma unroll
            for (int mt = 0; mt < 4; mt++) {
                const int row = warp_m * 64 + mt * 16 + a_mloc;
                const uint32_t sw = SWZ((uint32_t)(row * 128 + ks * 32 + a_kh * 16));
                ldsm4(ah[mt], base + sw);
            }
#pragma unroll
            for (int np = 0; np < 2; np++) {
                const int row = warp_n * 32 + np * 16 + b_nloc;
                const uint32_t sw = SWZ((uint32_t)(row * 128 + ks * 32 + b_kh * 16));
                ldsm4(bh[np], base + TILE_B + sw);
            }
#pragma unroll
            for (int mt = 0; mt < 4; mt++)
#pragma unroll
                for (int nt = 0; nt < 4; nt++)
                    mma16816(acc[mt][nt], ah[mt],
                             bh[nt >> 1][(nt & 1) * 2], bh[nt >> 1][(nt & 1) * 2 + 1]);
        }
    }

#pragma unroll
    for (int mt = 0; mt < 4; mt++) {
        const int row = bm + warp_m * 64 + mt * 16 + (lane >> 2);
#pragma unroll
        for (int nt = 0; nt < 4; nt++) {
            const int col = bn + warp_n * 32 + nt * 8 + (lane & 3) * 2;
            const float2 bb = *(const float2*)(bias + col);
            const float c00 = acc[mt][nt][0] + bb.x;
            const float c01 = acc[mt][nt][1] + bb.y;
            const float c10 = acc[mt][nt][2] + bb.x;
            const float c11 = acc[mt][nt][3] + bb.y;
            if (OUT_FP16) {
                *(uint32_t*)(Ch + (size_t)row * N + col)       = pack_hi(c00, c01);
                *(uint32_t*)(Ch + (size_t)(row + 8) * N + col) = pack_hi(c10, c11);
            } else {
                *(float2*)(C + (size_t)row * N + col)       = make_float2(c00, c01);
                *(float2*)(C + (size_t)(row + 8) * N + col) = make_float2(c10, c11);
            }
        }
    }
}

// ---------------------------------------------------------------------------
// HMMA flash attention, fully fp16 single-pass: S = Qh Kh^T, O += Ph Vh.
// CTA: 64 q-rows x (head, batch), 128 threads (4 warps x 16 rows),
// 3 CTAs/SM (~42KB smem). y written as fp16. (Unchanged from round 13.)
// ---------------------------------------------------------------------------
#define KTILE_B   8192           // 64 rows * 128 B
#define ASTAGE_B  (2 * KTILE_B)  // Kh + Vh = 16 KB
#define ASMEM     (8192 + 2 * ASTAGE_B + 1024)

__global__ __launch_bounds__(128, 3) void attn_hmma(
    const __half* __restrict__ Gh, __half* __restrict__ Yh)
{
    extern __shared__ char smr[];
    const uint32_t sb  = (smem_u32(smr) + 1023u) & ~1023u;
    const uint32_t sQh = sb;
    const uint32_t sKV = sb + 8192;

    const int t = threadIdx.x;
    const int lane = t & 31, wid = t >> 5;
    const int lg = lane >> 3, lr = lane & 7;
    const int a_mloc = (lg & 1) * 8 + lr, a_kh = lg >> 1;
    const int b_nloc = (lg >> 1) * 8 + lr, b_kh = lg & 1;

    const int qt = gridDim.x - 1 - blockIdx.x;   // heaviest first
    const int h  = blockIdx.y;
    const int b  = blockIdx.z;

    const size_t qrow0 = (size_t)b * SEQ + qt * 64;
    const size_t hoff  = (size_t)h * HDIM;

    auto fill = [&](int kb, int st) {
        const uint32_t base = sKV + st * ASTAGE_B;
#pragma unroll
        for (int l = 0; l < 4; l++) {
            const int idx = t + 128 * l;
            const int row = idx >> 3, ch = idx & 7;
            const uint32_t sw = SWZ((uint32_t)(row * 128 + ch * 16));
            const size_t g = ((size_t)b * SEQ + kb * 64 + row) * C3 + hoff + ch * 8;
            cpasync16(base + sw,           Gh + g + EMB);       // Kh
            cpasync16(base + KTILE_B + sw, Gh + g + 2 * EMB);   // Vh
        }
    };

    // prologue: Q tile + KV block 0 in one group
#pragma unroll
    for (int l = 0; l < 4; l++) {
        const int idx = t + 128 * l;
        const int row = idx >> 3, ch = idx & 7;
        const uint32_t sw = SWZ((uint32_t)(row * 128 + ch * 16));
        const size_t g = (qrow0 + row) * C3 + hoff + ch * 8;
        cpasync16(sQh + sw, Gh + g);
    }
    fill(0, 0);
    CP_COMMIT();
    CP_WAIT(0);
    __syncthreads();

    // Q fragments (registers, whole CTA lifetime)
    uint32_t qh[4][4];
#pragma unroll
    for (int ks = 0; ks < 4; ks++) {
        const int row = wid * 16 + a_mloc;
        const uint32_t sw = SWZ((uint32_t)(row * 128 + ks * 32 + a_kh * 16));
        ldsm4(qh[ks], sQh + sw);
    }

    float of[8][4];
#pragma unroll
    for (int i = 0; i < 8; i++)
#pragma unroll
        for (int e = 0; e < 4; e++) of[i][e] = 0.0f;
    float m_run[2] = {-1e30f, -1e30f};
    float l_run[2] = {0.0f, 0.0f};

    const int nkb = qt + 1;
    for (int kb = 0; kb < nkb; kb++) {
        if (kb + 1 < nkb) {
            fill(kb + 1, (kb + 1) & 1);
            CP_COMMIT();
        }

        const uint32_t kbase = sKV + (kb & 1) * ASTAGE_B;

        // ---- S = Qh Kh^T (1 pass) ----
        float sf[8][4];
#pragma unroll
        for (int i = 0; i < 8; i++)
#pragma unroll
            for (int e = 0; e < 4; e++) sf[i][e] = 0.0f;

#pragma unroll
        for (int ks = 0; ks < 4; ks++) {
            uint32_t kh4[4][4];
#pragma unroll
            for (int g = 0; g < 4; g++) {
                const int row = g * 16 + b_nloc;
                const uint32_t sw = SWZ((uint32_t)(row * 128 + ks * 32 + b_kh * 16));
                ldsm4(kh4[g], kbase + sw);
            }
#pragma unroll
            for (int nt = 0; nt < 8; nt++)
                mma16816(sf[nt], qh[ks], kh4[nt >> 1][(nt & 1) * 2],
                         kh4[nt >> 1][(nt & 1) * 2 + 1]);
        }

        // ---- online softmax ----
        const bool diag = (kb == qt);
#pragma unroll
        for (int half = 0; half < 2; half++) {
            const int rowg = qt * 64 + wid * 16 + (lane >> 2) + half * 8;
            float mx = -1e30f;
#pragma unroll
            for (int nt = 0; nt < 8; nt++)
#pragma unroll
                for (int e = 0; e < 2; e++) {
                    float v = sf[nt][half * 2 + e] * 0.125f;
                    if (diag) {
                        const int colg = kb * 64 + nt * 8 + (lane & 3) * 2 + e;
                        if (colg > rowg) v = -1e30f;
                    }
                    sf[nt][half * 2 + e] = v;
                    mx = fmaxf(mx, v);
                }
            mx = fmaxf(mx, __shfl_xor_sync(0xffffffffu, mx, 1));
            mx = fmaxf(mx, __shfl_xor_sync(0xffffffffu, mx, 2));
            const float m_new = fmaxf(m_run[half], mx);
            const float corr  = __expf(m_run[half] - m_new);
            float ls = 0.0f;
#pragma unroll
            for (int nt = 0; nt < 8; nt++)
#pragma unroll
                for (int e = 0; e < 2; e++) {
                    const float p = __expf(sf[nt][half * 2 + e] - m_new);
                    sf[nt][half * 2 + e] = p;
                    ls += p;
                }
            l_run[half] = l_run[half] * corr + ls;   // lane-partial
            m_run[half] = m_new;
#pragma unroll
            for (int dt = 0; dt < 8; dt++) {
                of[dt][half * 2]     *= corr;
                of[dt][half * 2 + 1] *= corr;
            }
        }

        // ---- O += Ph Vh (1 pass) ----
        const uint32_t vbase = kbase + KTILE_B;
#pragma unroll
        for (int kc = 0; kc < 4; kc++) {
            uint32_t pa_h[4];
            pa_h[0] = pack_hi(sf[kc * 2][0],     sf[kc * 2][1]);
            pa_h[1] = pack_hi(sf[kc * 2][2],     sf[kc * 2][3]);
            pa_h[2] = pack_hi(sf[kc * 2 + 1][0], sf[kc * 2 + 1][1]);
            pa_h[3] = pack_hi(sf[kc * 2 + 1][2], sf[kc * 2 + 1][3]);

            uint32_t vh4[4][4];
#pragma unroll
            for (int dc = 0; dc < 4; dc++) {
                const int krow = kc * 16 + (lg & 1) * 8 + lr;
                const uint32_t sw =
                    SWZ((uint32_t)(krow * 128 + (dc * 16 + (lg >> 1) * 8) * 2));
                ldsm4t(vh4[dc], vbase + sw);
            }
#pragma unroll
            for (int dt = 0; dt < 8; dt++)
                mma16816(of[dt], pa_h, vh4[dt >> 1][(dt & 1) * 2],
                         vh4[dt >> 1][(dt & 1) * 2 + 1]);
        }

        if (kb + 1 < nkb) {
            CP_WAIT(0);
            __syncthreads();
        }
    }

    // ---- epilogue: y as fp16 ----
    float inv[2];
#pragma unroll
    for (int half = 0; half < 2; half++) {
        float l = l_run[half];
        l += __shfl_xor_sync(0xffffffffu, l, 1);
        l += __shfl_xor_sync(0xffffffffu, l, 2);
        inv[half] = 1.0f / l;
    }
    const size_t orow = qrow0 + wid * 16 + (lane >> 2);
    const size_t obase = orow * EMB + hoff + (lane & 3) * 2;
#pragma unroll
    for (int dt = 0; dt < 8; dt++) {
        *(uint32_t*)(Yh + obase + dt * 8) =
            pack_hi(of[dt][0] * inv[0], of[dt][1] * inv[0]);
        *(uint32_t*)(Yh + obase + 8 * EMB + dt * 8) =
            pack_hi(of[dt][2] * inv[1], of[dt][3] * inv[1]);
    }
}

// ---------------------------------------------------------------------------
// Launch
// ---------------------------------------------------------------------------
extern "C" void kernel_launch(void* const* d_in, const int* in_sizes, int n_in,
                              void* d_out, int out_size)
{
    const float* x      = (const float*)d_in[0];
    const float* w_attn = (const float*)d_in[1];
    const float* b_attn = (const float*)d_in[2];
    const float* w_proj = (const float*)d_in[3];
    const float* b_proj = (const float*)d_in[4];
    float* out = (float*)d_out;

    void* p;
    cudaGetSymbolAddress(&p, g_x_h);    __half* x_h   = (__half*)p;
    cudaGetSymbolAddress(&p, g_wa_h);   __half* wa_h  = (__half*)p;
    cudaGetSymbolAddress(&p, g_wp_h);   __half* wp_h  = (__half*)p;
    cudaGetSymbolAddress(&p, g_qkv_h);  __half* qkv_h = (__half*)p;
    cudaGetSymbolAddress(&p, g_y_h);    __half* y_h   = (__half*)p;

    cudaFuncSetAttribute(gemm_hmma<true>,
                         cudaFuncAttributeMaxDynamicSharedMemorySize, GSMEM);
    cudaFuncSetAttribute(gemm_hmma<false>,
                         cudaFuncAttributeMaxDynamicSharedMemorySize, GSMEM);
    cudaFuncSetAttribute(attn_hmma,
                         cudaFuncAttributeMaxDynamicSharedMemorySize, ASMEM);

    // 0) fp32 -> fp16 conversions
    {
        int n4 = MTOT * EMB / 4;
        split_kernel<<<n4 / 256, 256>>>((const float4*)x, (uint2*)x_h, n4);
        n4 = C3 * EMB / 4;
        split_kernel<<<n4 / 256, 256>>>((const float4*)w_attn, (uint2*)wa_h, n4);
        n4 = EMB * EMB / 4;
        split_kernel<<<n4 / 256, 256>>>((const float4*)w_proj, (uint2*)wp_h, n4);
    }

    // 1) qkv = x @ w_attn^T + b_attn (fp16 out)
    {
        dim3 grid(C3 / 128, MTOT / 128);
        gemm_hmma<true><<<grid, 256, GSMEM>>>(x_h, wa_h, b_attn,
                                              nullptr, qkv_h, MTOT, C3, EMB);
    }

    // 2) HMMA flash attention -> fp16 y
    {
        dim3 grid(SEQ / 64, HEADS, BATCH);
        attn_hmma<<<grid, 128, ASMEM>>>(qkv_h, y_h);
    }

    // 3) out = y @ w_proj^T + b_proj (fp32 out)
    {
        dim3 grid(EMB / 128, MTOT / 128);
        gemm_hmma<false><<<grid, 256, GSMEM>>>(y_h, wp_h, b_proj,
                                               out, nullptr, MTOT, EMB, EMB);
    }
}

// round 15
// speedup vs baseline: 2.5013x; 1.0061x over previous
#include <cuda_runtime.h>
#include <cuda_fp16.h>
#include <cstdint>

// Problem constants
#define BATCH 2
#define SEQ   2048
#define EMB   1024
#define HEADS 16
#define HDIM  64
#define C3    (3 * EMB)
#define MTOT  (BATCH * SEQ)   // 4096

// Scratch (allocation-free rule: __device__ globals), fp16 operands
__device__ __half g_x_h[MTOT * EMB];
__device__ __half g_wa_h[C3 * EMB];
__device__ __half g_wp_h[EMB * EMB];
__device__ __half g_qkv_h[MTOT * C3];
__device__ __half g_y_h[MTOT * EMB];

// ---------------------------------------------------------------------------
// helpers (plain sm_80-level PTX: valid at compute_103)
// ---------------------------------------------------------------------------
__device__ __forceinline__ uint32_t smem_u32(const void* p) {
    uint32_t a;
    asm("{ .reg .u64 t; cvta.to.shared.u64 t, %1; cvt.u32.u64 %0, t; }"
        : "=r"(a) : "l"(p));
    return a;
}

__device__ __forceinline__ void cpasync16(uint32_t dst, const void* src) {
    asm volatile("cp.async.cg.shared.global [%0], [%1], 16;"
                 :: "r"(dst), "l"(src) : "memory");
}
#define CP_COMMIT() asm volatile("cp.async.commit_group;" ::: "memory")
#define CP_WAIT(n)  asm volatile("cp.async.wait_group %0;" :: "n"(n) : "memory")

__device__ __forceinline__ void ldsm4(uint32_t* r, uint32_t addr) {
    asm volatile("ldmatrix.sync.aligned.m8n8.x4.shared.b16 {%0,%1,%2,%3}, [%4];"
                 : "=r"(r[0]), "=r"(r[1]), "=r"(r[2]), "=r"(r[3]) : "r"(addr));
}
__device__ __forceinline__ void ldsm4t(uint32_t* r, uint32_t addr) {
    asm volatile("ldmatrix.sync.aligned.m8n8.x4.trans.shared.b16 {%0,%1,%2,%3}, [%4];"
                 : "=r"(r[0]), "=r"(r[1]), "=r"(r[2]), "=r"(r[3]) : "r"(addr));
}

__device__ __forceinline__ void mma16816(float* c, const uint32_t* a,
                                         uint32_t b0, uint32_t b1) {
    asm volatile(
        "mma.sync.aligned.m16n8k16.row.col.f32.f16.f16.f32 "
        "{%0,%1,%2,%3}, {%4,%5,%6,%7}, {%8,%9}, {%0,%1,%2,%3};"
        : "+f"(c[0]), "+f"(c[1]), "+f"(c[2]), "+f"(c[3])
        : "r"(a[0]), "r"(a[1]), "r"(a[2]), "r"(a[3]), "r"(b0), "r"(b1));
}

#define SWZ(o) ((o) ^ (((o) >> 3) & 0x70))

__device__ __forceinline__ uint32_t pack_hi(float x, float y) {
    __half2 h = __float22half2_rn(make_float2(x, y));
    return *(uint32_t*)&h;
}

__device__ __forceinline__ float ex2f(float x) {
    float r;
    asm("ex2.approx.f32 %0, %1;" : "=f"(r) : "f"(x));
    return r;
}

// ---------------------------------------------------------------------------
// convert fp32 -> fp16
// ---------------------------------------------------------------------------
__global__ __launch_bounds__(256) void split_kernel(
    const float4* __restrict__ in, uint2* __restrict__ hi, int n4)
{
    const int i = blockIdx.x * 256 + threadIdx.x;
    if (i >= n4) return;
    const float4 v = in[i];
    hi[i] = make_uint2(pack_hi(v.x, v.y), pack_hi(v.z, v.w));
}

// ---------------------------------------------------------------------------
// HMMA NT GEMM, fp16 single-pass: C = Ah @ Bh^T + bias.
// 128 threads, 4 warps (2x2), warp tile 64x64. CTA 128x128, BK=64.
// 2-stage cp.async ring (32 KB/stage) -> 66 KB smem -> 2 CTAs/SM.
// Fragment economy: per warp-ks 8 ldsm.x4 : 32 MMA (4:1).
// ---------------------------------------------------------------------------
#define TILE_B  16384
#define STAGE_B (2 * TILE_B)            // Ah, Bh
#define GSMEM   (2 * STAGE_B + 1024)    // 66.5 KB

template<bool OUT_FP16>
__global__ __launch_bounds__(128, 2) void gemm_hmma(
    const __half* __restrict__ Ah, const __half* __restrict__ Bh,
    const float* __restrict__ bias, float* __restrict__ C,
    __half* __restrict__ Ch,
    int M, int N, int K)
{
    extern __shared__ char smr[];
    const uint32_t sb = (smem_u32(smr) + 1023u) & ~1023u;

    const int t    = threadIdx.x;
    const int lane = t & 31;
    const int wid  = t >> 5;
    const int warp_m = wid & 1;     // 0..1 (64 rows each)
    const int warp_n = wid >> 1;    // 0..1 (64 cols each)
    const int bm = blockIdx.y * 128;
    const int bn = blockIdx.x * 128;

    const int lg = lane >> 3, lr = lane & 7;
    const int a_mloc = (lg & 1) * 8 + lr;  const int a_kh = lg >> 1;
    const int b_nloc = (lg >> 1) * 8 + lr; const int b_kh = lg & 1;

    const int NC = K >> 6;

    auto issue = [&](int kt, int stage) {
        const uint32_t base = sb + stage * STAGE_B;
        const int k0 = kt << 6;
#pragma unroll
        for (int l = 0; l < 8; l++) {
            const int idx = t + 128 * l;
            const int row = idx >> 3;
            const int ch  = idx & 7;
            const uint32_t sw = SWZ((uint32_t)(row * 128 + ch * 16));
            const size_t ga = (size_t)(bm + row) * K + k0 + ch * 8;
            const size_t gb = (size_t)(bn + row) * K + k0 + ch * 8;
            cpasync16(base + sw,          Ah + ga);
            cpasync16(base + TILE_B + sw, Bh + gb);
        }
    };

    float acc[4][8][4];
#pragma unroll
    for (int i = 0; i < 4; i++)
#pragma unroll
        for (int j = 0; j < 8; j++)
#pragma unroll
            for (int e = 0; e < 4; e++) acc[i][j][e] = 0.0f;

    issue(0, 0); CP_COMMIT();

    for (int kt = 0; kt < NC; kt++) {
        CP_WAIT(0);            // group kt is the only outstanding one
        __syncthreads();       // all warps past compute(kt-1); stage safe
        if (kt + 1 < NC) {
            issue(kt + 1, (kt + 1) & 1);   // overlaps compute(kt)
            CP_COMMIT();
        }

        const uint32_t base = sb + (kt & 1) * STAGE_B;
#pragma unroll
        for (int ks = 0; ks < 4; ks++) {
            uint32_t ah[4][4], bh[4][4];
#pragma unroll
            for (int mt = 0; mt < 4; mt++) {
                const int row = warp_m * 64 + mt * 16 + a_mloc;
                const uint32_t sw = SWZ((uint32_t)(row * 128 + ks * 32 + a_kh * 16));
                ldsm4(ah[mt], base + sw);
            }
#pragma unroll
            for (int np = 0; np < 4; np++) {
                const int row = warp_n * 64 + np * 16 + b_nloc;
                const uint32_t sw = SWZ((uint32_t)(row * 128 + ks * 32 + b_kh * 16));
                ldsm4(bh[np], base + TILE_B + sw);
            }
#pragma unroll
            for (int mt = 0; mt < 4; mt++)
#pragma unroll
                for (int nt = 0; nt < 8; nt++)
                    mma16816(acc[mt][nt], ah[mt],
                             bh[nt >> 1][(nt & 1) * 2], bh[nt >> 1][(nt & 1) * 2 + 1]);
        }
    }

#pragma unroll
    for (int mt = 0; mt < 4; mt++) {
        const int row = bm + warp_m * 64 + mt * 16 + (lane >> 2);
#pragma unroll
        for (int nt = 0; nt < 8; nt++) {
            const int col = bn + warp_n * 64 + nt * 8 + (lane & 3) * 2;
            const float2 bb = *(const float2*)(bias + col);
            const float c00 = acc[mt][nt][0] + bb.x;
            const float c01 = acc[mt][nt][1] + bb.y;
            const float c10 = acc[mt][nt][2] + bb.x;
            const float c11 = acc[mt][nt][3] + bb.y;
            if (OUT_FP16) {
                *(uint32_t*)(Ch + (size_t)row * N + col)       = pack_hi(c00, c01);
                *(uint32_t*)(Ch + (size_t)(row + 8) * N + col) = pack_hi(c10, c11);
            } else {
                *(float2*)(C + (size_t)row * N + col)       = make_float2(c00, c01);
                *(float2*)(C + (size_t)(row + 8) * N + col) = make_float2(c10, c11);
            }
        }
    }
}

// ---------------------------------------------------------------------------
// HMMA flash attention, fp16 single-pass, log2-domain softmax.
// CTA: 64 q-rows x (head, batch), 128 threads (4 warps x 16 rows),
// 3 CTAs/SM (~42KB smem). y written as fp16.
// ---------------------------------------------------------------------------
#define KTILE_B   8192           // 64 rows * 128 B
#define ASTAGE_B  (2 * KTILE_B)  // Kh + Vh = 16 KB
#define ASMEM     (8192 + 2 * ASTAGE_B + 1024)

// scale * log2(e) = 0.125 * 1.4426950408889634
#define SCALE_LOG2E 0.18033688011112043f

__global__ __launch_bounds__(128, 3) void attn_hmma(
    const __half* __restrict__ Gh, __half* __restrict__ Yh)
{
    extern __shared__ char smr[];
    const uint32_t sb  = (smem_u32(smr) + 1023u) & ~1023u;
    const uint32_t sQh = sb;
    const uint32_t sKV = sb + 8192;

    const int t = threadIdx.x;
    const int lane = t & 31, wid = t >> 5;
    const int lg = lane >> 3, lr = lane & 7;
    const int a_mloc = (lg & 1) * 8 + lr, a_kh = lg >> 1;
    const int b_nloc = (lg >> 1) * 8 + lr, b_kh = lg & 1;

    const int qt = gridDim.x - 1 - blockIdx.x;   // heaviest first
    const int h  = blockIdx.y;
    const int b  = blockIdx.z;

    const size_t qrow0 = (size_t)b * SEQ + qt * 64;
    const size_t hoff  = (size_t)h * HDIM;

    auto fill = [&](int kb, int st) {
        const uint32_t base = sKV + st * ASTAGE_B;
#pragma unroll
        for (int l = 0; l < 4; l++) {
            const int idx = t + 128 * l;
            const int row = idx >> 3, ch = idx & 7;
            const uint32_t sw = SWZ((uint32_t)(row * 128 + ch * 16));
            const size_t g = ((size_t)b * SEQ + kb * 64 + row) * C3 + hoff + ch * 8;
            cpasync16(base + sw,           Gh + g + EMB);       // Kh
            cpasync16(base + KTILE_B + sw, Gh + g + 2 * EMB);   // Vh
        }
    };

    // prologue: Q tile + KV block 0 in one group
#pragma unroll
    for (int l = 0; l < 4; l++) {
        const int idx = t + 128 * l;
        const int row = idx >> 3, ch = idx & 7;
        const uint32_t sw = SWZ((uint32_t)(row * 128 + ch * 16));
        const size_t g = (qrow0 + row) * C3 + hoff + ch * 8;
        cpasync16(sQh + sw, Gh + g);
    }
    fill(0, 0);
    CP_COMMIT();
    CP_WAIT(0);
    __syncthreads();

    // Q fragments (registers, whole CTA lifetime)
    uint32_t qh[4][4];
#pragma unroll
    for (int ks = 0; ks < 4; ks++) {
        const int row = wid * 16 + a_mloc;
        const uint32_t sw = SWZ((uint32_t)(row * 128 + ks * 32 + a_kh * 16));
        ldsm4(qh[ks], sQh + sw);
    }

    float of[8][4];
#pragma unroll
    for (int i = 0; i < 8; i++)
#pragma unroll
        for (int e = 0; e < 4; e++) of[i][e] = 0.0f;
    float m_run[2] = {-1e30f, -1e30f};   // log2-domain running max
    float l_run[2] = {0.0f, 0.0f};

    const int nkb = qt + 1;
    for (int kb = 0; kb < nkb; kb++) {
        if (kb + 1 < nkb) {
            fill(kb + 1, (kb + 1) & 1);
            CP_COMMIT();
        }

        const uint32_t kbase = sKV + (kb & 1) * ASTAGE_B;

        // ---- S = Qh Kh^T (1 pass) ----
        float sf[8][4];
#pragma unroll
        for (int i = 0; i < 8; i++)
#pragma unroll
            for (int e = 0; e < 4; e++) sf[i][e] = 0.0f;

#pragma unroll
        for (int ks = 0; ks < 4; ks++) {
            uint32_t kh4[4][4];
#pragma unroll
            for (int g = 0; g < 4; g++) {
                const int row = g * 16 + b_nloc;
                const uint32_t sw = SWZ((uint32_t)(row * 128 + ks * 32 + b_kh * 16));
                ldsm4(kh4[g], kbase + sw);
            }
#pragma unroll
            for (int nt = 0; nt < 8; nt++)
                mma16816(sf[nt], qh[ks], kh4[nt >> 1][(nt & 1) * 2],
                         kh4[nt >> 1][(nt & 1) * 2 + 1]);
        }

        // ---- online softmax (log2 domain: p = 2^(s*SCALE_LOG2E - m)) ----
        const bool diag = (kb == qt);
#pragma unroll
        for (int half = 0; half < 2; half++) {
            const int rowg = qt * 64 + wid * 16 + (lane >> 2) + half * 8;
            float mx = -1e30f;
#pragma unroll
            for (int nt = 0; nt < 8; nt++)
#pragma unroll
                for (int e = 0; e < 2; e++) {
                    float v = sf[nt][half * 2 + e] * SCALE_LOG2E;
                    if (diag) {
                        const int colg = kb * 64 + nt * 8 + (lane & 3) * 2 + e;
                        if (colg > rowg) v = -1e30f;
                    }
                    sf[nt][half * 2 + e] = v;
                    mx = fmaxf(mx, v);
                }
            mx = fmaxf(mx, __shfl_xor_sync(0xffffffffu, mx, 1));
            mx = fmaxf(mx, __shfl_xor_sync(0xffffffffu, mx, 2));
            const float m_new = fmaxf(m_run[half], mx);
            const float corr  = ex2f(m_run[half] - m_new);
            float ls = 0.0f;
#pragma unroll
            for (int nt = 0; nt < 8; nt++)
#pragma unroll
                for (int e = 0; e < 2; e++) {
                    const float p = ex2f(sf[nt][half * 2 + e] - m_new);
                    sf[nt][half * 2 + e] = p;
                    ls += p;
                }
            l_run[half] = l_run[half] * corr + ls;   // lane-partial
            m_run[half] = m_new;
#pragma unroll
            for (int dt = 0; dt < 8; dt++) {
                of[dt][half * 2]     *= corr;
                of[dt][half * 2 + 1] *= corr;
            }
        }

        // ---- O += Ph Vh (1 pass) ----
        const uint32_t vbase = kbase + KTILE_B;
#pragma unroll
        for (int kc = 0; kc < 4; kc++) {
            uint32_t pa_h[4];
            pa_h[0] = pack_hi(sf[kc * 2][0],     sf[kc * 2][1]);
            pa_h[1] = pack_hi(sf[kc * 2][2],     sf[kc * 2][3]);
            pa_h[2] = pack_hi(sf[kc * 2 + 1][0], sf[kc * 2 + 1][1]);
            pa_h[3] = pack_hi(sf[kc * 2 + 1][2], sf[kc * 2 + 1][3]);

            uint32_t vh4[4][4];
#pragma unroll
            for (int dc = 0; dc < 4; dc++) {
                const int krow = kc * 16 + (lg & 1) * 8 + lr;
                const uint32_t sw =
                    SWZ((uint32_t)(krow * 128 + (dc * 16 + (lg >> 1) * 8) * 2));
                ldsm4t(vh4[dc], vbase + sw);
            }
#pragma unroll
            for (int dt = 0; dt < 8; dt++)
                mma16816(of[dt], pa_h, vh4[dt >> 1][(dt & 1) * 2],
                         vh4[dt >> 1][(dt & 1) * 2 + 1]);
        }

        if (kb + 1 < nkb) {
            CP_WAIT(0);
            __syncthreads();
        }
    }

    // ---- epilogue: y as fp16 ----
    float inv[2];
#pragma unroll
    for (int half = 0; half < 2; half++) {
        float l = l_run[half];
        l += __shfl_xor_sync(0xffffffffu, l, 1);
        l += __shfl_xor_sync(0xffffffffu, l, 2);
        inv[half] = 1.0f / l;
    }
    const size_t orow = qrow0 + wid * 16 + (lane >> 2);
    const size_t obase = orow * EMB + hoff + (lane & 3) * 2;
#pragma unroll
    for (int dt = 0; dt < 8; dt++) {
        *(uint32_t*)(Yh + obase + dt * 8) =
            pack_hi(of[dt][0] * inv[0], of[dt][1] * inv[0]);
        *(uint32_t*)(Yh + obase + 8 * EMB + dt * 8) =
            pack_hi(of[dt][2] * inv[1], of[dt][3] * inv[1]);
    }
}

// ---------------------------------------------------------------------------
// Launch
// ---------------------------------------------------------------------------
extern "C" void kernel_launch(void* const* d_in, const int* in_sizes, int n_in,
                              void* d_out, int out_size)
{
    const float* x      = (const float*)d_in[0];
    const float* w_attn = (const float*)d_in[1];
    const float* b_attn = (const float*)d_in[2];
    const float* w_proj = (const float*)d_in[3];
    const float* b_proj = (const float*)d_in[4];
    float* out = (float*)d_out;

    void* p;
    cudaGetSymbolAddress(&p, g_x_h);    __half* x_h   = (__half*)p;
    cudaGetSymbolAddress(&p, g_wa_h);   __half* wa_h  = (__half*)p;
    cudaGetSymbolAddress(&p, g_wp_h);   __half* wp_h  = (__half*)p;
    cudaGetSymbolAddress(&p, g_qkv_h);  __half* qkv_h = (__half*)p;
    cudaGetSymbolAddress(&p, g_y_h);    __half* y_h   = (__half*)p;

    cudaFuncSetAttribute(gemm_hmma<true>,
                         cudaFuncAttributeMaxDynamicSharedMemorySize, GSMEM);
    cudaFuncSetAttribute(gemm_hmma<false>,
                         cudaFuncAttributeMaxDynamicSharedMemorySize, GSMEM);
    cudaFuncSetAttribute(attn_hmma,
                         cudaFuncAttributeMaxDynamicSharedMemorySize, ASMEM);

    // 0) fp32 -> fp16 conversions
    {
        int n4 = MTOT * EMB / 4;
        split_kernel<<<n4 / 256, 256>>>((const float4*)x, (uint2*)x_h, n4);
        n4 = C3 * EMB / 4;
        split_kernel<<<n4 / 256, 256>>>((const float4*)w_attn, (uint2*)wa_h, n4);
        n4 = EMB * EMB / 4;
        split_kernel<<<n4 / 256, 256>>>((const float4*)w_proj, (uint2*)wp_h, n4);
    }

    // 1) qkv = x @ w_attn^T + b_attn (fp16 out)
    {
        dim3 grid(C3 / 128, MTOT / 128);
        gemm_hmma<true><<<grid, 128, GSMEM>>>(x_h, wa_h, b_attn,
                                              nullptr, qkv_h, MTOT, C3, EMB);
    }

    // 2) HMMA flash attention -> fp16 y
    {
        dim3 grid(SEQ / 64, HEADS, BATCH);
        attn_hmma<<<grid, 128, ASMEM>>>(qkv_h, y_h);
    }

    // 3) out = y @ w_proj^T + b_proj (fp32 out)
    {
        dim3 grid(EMB / 128, MTOT / 128);
        gemm_hmma<false><<<grid, 128, GSMEM>>>(y_h, wp_h, b_proj,
                                               out, nullptr, MTOT, EMB, EMB);
    }
}

// round 16
// speedup vs baseline: 2.5451x; 1.0175x over previous
#include <cuda_runtime.h>
#include <cuda_fp16.h>
#include <cstdint>

// Problem constants
#define BATCH 2
#define SEQ   2048
#define EMB   1024
#define HEADS 16
#define HDIM  64
#define C3    (3 * EMB)
#define MTOT  (BATCH * SEQ)   // 4096

// Scratch (allocation-free rule: __device__ globals), fp16 operands
__device__ __half g_x_h[MTOT * EMB];
__device__ __half g_wa_h[C3 * EMB];
__device__ __half g_wp_h[EMB * EMB];
__device__ __half g_qkv_h[MTOT * C3];
__device__ __half g_y_h[MTOT * EMB];

// ---------------------------------------------------------------------------
// helpers (plain sm_80-level PTX: valid at compute_103)
// ---------------------------------------------------------------------------
__device__ __forceinline__ uint32_t smem_u32(const void* p) {
    uint32_t a;
    asm("{ .reg .u64 t; cvta.to.shared.u64 t, %1; cvt.u32.u64 %0, t; }"
        : "=r"(a) : "l"(p));
    return a;
}

__device__ __forceinline__ void cpasync16(uint32_t dst, const void* src) {
    asm volatile("cp.async.cg.shared.global [%0], [%1], 16;"
                 :: "r"(dst), "l"(src) : "memory");
}
#define CP_COMMIT() asm volatile("cp.async.commit_group;" ::: "memory")
#define CP_WAIT(n)  asm volatile("cp.async.wait_group %0;" :: "n"(n) : "memory")

__device__ __forceinline__ void ldsm4(uint32_t* r, uint32_t addr) {
    asm volatile("ldmatrix.sync.aligned.m8n8.x4.shared.b16 {%0,%1,%2,%3}, [%4];"
                 : "=r"(r[0]), "=r"(r[1]), "=r"(r[2]), "=r"(r[3]) : "r"(addr));
}
__device__ __forceinline__ void ldsm4t(uint32_t* r, uint32_t addr) {
    asm volatile("ldmatrix.sync.aligned.m8n8.x4.trans.shared.b16 {%0,%1,%2,%3}, [%4];"
                 : "=r"(r[0]), "=r"(r[1]), "=r"(r[2]), "=r"(r[3]) : "r"(addr));
}

__device__ __forceinline__ void mma16816(float* c, const uint32_t* a,
                                         uint32_t b0, uint32_t b1) {
    asm volatile(
        "mma.sync.aligned.m16n8k16.row.col.f32.f16.f16.f32 "
        "{%0,%1,%2,%3}, {%4,%5,%6,%7}, {%8,%9}, {%0,%1,%2,%3};"
        : "+f"(c[0]), "+f"(c[1]), "+f"(c[2]), "+f"(c[3])
        : "r"(a[0]), "r"(a[1]), "r"(a[2]), "r"(a[3]), "r"(b0), "r"(b1));
}

#define SWZ(o) ((o) ^ (((o) >> 3) & 0x70))

__device__ __forceinline__ uint32_t pack_hi(float x, float y) {
    __half2 h = __float22half2_rn(make_float2(x, y));
    return *(uint32_t*)&h;
}

__device__ __forceinline__ float ex2f(float x) {
    float r;
    asm("ex2.approx.f32 %0, %1;" : "=f"(r) : "f"(x));
    return r;
}

// ---------------------------------------------------------------------------
// convert fp32 -> fp16
// ---------------------------------------------------------------------------
__global__ __launch_bounds__(256) void split_kernel(
    const float4* __restrict__ in, uint2* __restrict__ hi, int n4)
{
    const int i = blockIdx.x * 256 + threadIdx.x;
    if (i >= n4) return;
    const float4 v = in[i];
    hi[i] = make_uint2(pack_hi(v.x, v.y), pack_hi(v.z, v.w));
}

// ---------------------------------------------------------------------------
// HMMA NT GEMM, fp16 single-pass: C = Ah @ Bh^T + bias.
// CTA tile 128x64, 128 threads, 4 warps (2x2), warp tile 64x32. BK=64.
// 2-stage cp.async ring (24 KB/stage, ~49 KB smem) -> 3 CTAs/SM
// (reg budget: acc 64 + frags 24 + addr ~= 120 regs; 128x3x128 = 49K RF).
// Race-free single-sync order: wait(0) -> sync -> issue(kt+1) -> compute(kt).
// ---------------------------------------------------------------------------
#define A_TILE_B 16384                    // 128 rows * 128 B
#define B_TILE_B 8192                     // 64 rows * 128 B
#define STAGE_B  (A_TILE_B + B_TILE_B)    // 24 KB
#define GSMEM    (2 * STAGE_B + 1024)     // ~49 KB

template<bool OUT_FP16>
__global__ __launch_bounds__(128, 3) void gemm_hmma(
    const __half* __restrict__ Ah, const __half* __restrict__ Bh,
    const float* __restrict__ bias, float* __restrict__ C,
    __half* __restrict__ Ch,
    int M, int N, int K)
{
    extern __shared__ char smr[];
    const uint32_t sb = (smem_u32(smr) + 1023u) & ~1023u;

    const int t    = threadIdx.x;
    const int lane = t & 31;
    const int wid  = t >> 5;
    const int warp_m = wid & 1;     // 0..1 (64 rows each)
    const int warp_n = wid >> 1;    // 0..1 (32 cols each)
    const int bm = blockIdx.y * 128;
    const int bn = blockIdx.x * 64;

    const int lg = lane >> 3, lr = lane & 7;
    const int a_mloc = (lg & 1) * 8 + lr;  const int a_kh = lg >> 1;
    const int b_nloc = (lg >> 1) * 8 + lr; const int b_kh = lg & 1;

    const int NC = K >> 6;

    auto issue = [&](int kt, int stage) {
        const uint32_t base = sb + stage * STAGE_B;
        const int k0 = kt << 6;
        // A tile: 128 rows x 8 chunks = 1024 chunks, 8 per thread
#pragma unroll
        for (int l = 0; l < 8; l++) {
            const int idx = t + 128 * l;
            const int row = idx >> 3;
            const int ch  = idx & 7;
            const uint32_t sw = SWZ((uint32_t)(row * 128 + ch * 16));
            cpasync16(base + sw, Ah + (size_t)(bm + row) * K + k0 + ch * 8);
        }
        // B tile: 64 rows x 8 chunks = 512 chunks, 4 per thread
#pragma unroll
        for (int l = 0; l < 4; l++) {
            const int idx = t + 128 * l;
            const int row = idx >> 3;
            const int ch  = idx & 7;
            const uint32_t sw = SWZ((uint32_t)(row * 128 + ch * 16));
            cpasync16(base + A_TILE_B + sw,
                      Bh + (size_t)(bn + row) * K + k0 + ch * 8);
        }
    };

    float acc[4][4][4];
#pragma unroll
    for (int i = 0; i < 4; i++)
#pragma unroll
        for (int j = 0; j < 4; j++)
#pragma unroll
            for (int e = 0; e < 4; e++) acc[i][j][e] = 0.0f;

    issue(0, 0); CP_COMMIT();

    for (int kt = 0; kt < NC; kt++) {
        CP_WAIT(0);            // group kt is the only outstanding one
        __syncthreads();       // all warps past compute(kt-1); stage safe
        if (kt + 1 < NC) {
            issue(kt + 1, (kt + 1) & 1);   // overlaps compute(kt)
            CP_COMMIT();
        }

        const uint32_t base = sb + (kt & 1) * STAGE_B;
#pragma unroll
        for (int ks = 0; ks < 4; ks++) {
            uint32_t ah[4][4], bh[2][4];
#pragma unroll
            for (int mt = 0; mt < 4; mt++) {
                const int row = warp_m * 64 + mt * 16 + a_mloc;
                const uint32_t sw = SWZ((uint32_t)(row * 128 + ks * 32 + a_kh * 16));
                ldsm4(ah[mt], base + sw);
            }
#pragma unroll
            for (int np = 0; np < 2; np++) {
                const int row = warp_n * 32 + np * 16 + b_nloc;
                const uint32_t sw = SWZ((uint32_t)(row * 128 + ks * 32 + b_kh * 16));
                ldsm4(bh[np], base + A_TILE_B + sw);
            }
#pragma unroll
            for (int mt = 0; mt < 4; mt++)
#pragma unroll
                for (int nt = 0; nt < 4; nt++)
                    mma16816(acc[mt][nt], ah[mt],
                             bh[nt >> 1][(nt & 1) * 2], bh[nt >> 1][(nt & 1) * 2 + 1]);
        }
    }

#pragma unroll
    for (int mt = 0; mt < 4; mt++) {
        const int row = bm + warp_m * 64 + mt * 16 + (lane >> 2);
#pragma unroll
        for (int nt = 0; nt < 4; nt++) {
            const int col = bn + warp_n * 32 + nt * 8 + (lane & 3) * 2;
            const float2 bb = *(const float2*)(bias + col);
            const float c00 = acc[mt][nt][0] + bb.x;
            const float c01 = acc[mt][nt][1] + bb.y;
            const float c10 = acc[mt][nt][2] + bb.x;
            const float c11 = acc[mt][nt][3] + bb.y;
            if (OUT_FP16) {
                *(uint32_t*)(Ch + (size_t)row * N + col)       = pack_hi(c00, c01);
                *(uint32_t*)(Ch + (size_t)(row + 8) * N + col) = pack_hi(c10, c11);
            } else {
                *(float2*)(C + (size_t)row * N + col)       = make_float2(c00, c01);
                *(float2*)(C + (size_t)(row + 8) * N + col) = make_float2(c10, c11);
            }
        }
    }
}

// ---------------------------------------------------------------------------
// HMMA flash attention, fp16 single-pass, log2-domain softmax.
// CTA: 64 q-rows x (head, batch), 128 threads (4 warps x 16 rows),
// 3 CTAs/SM (~42KB smem). y written as fp16. (Unchanged from round 15.)
// ---------------------------------------------------------------------------
#define KTILE_B   8192           // 64 rows * 128 B
#define ASTAGE_B  (2 * KTILE_B)  // Kh + Vh = 16 KB
#define ASMEM     (8192 + 2 * ASTAGE_B + 1024)

// scale * log2(e) = 0.125 * 1.4426950408889634
#define SCALE_LOG2E 0.18033688011112043f

__global__ __launch_bounds__(128, 3) void attn_hmma(
    const __half* __restrict__ Gh, __half* __restrict__ Yh)
{
    extern __shared__ char smr[];
    const uint32_t sb  = (smem_u32(smr) + 1023u) & ~1023u;
    const uint32_t sQh = sb;
    const uint32_t sKV = sb + 8192;

    const int t = threadIdx.x;
    const int lane = t & 31, wid = t >> 5;
    const int lg = lane >> 3, lr = lane & 7;
    const int a_mloc = (lg & 1) * 8 + lr, a_kh = lg >> 1;
    const int b_nloc = (lg >> 1) * 8 + lr, b_kh = lg & 1;

    const int qt = gridDim.x - 1 - blockIdx.x;   // heaviest first
    const int h  = blockIdx.y;
    const int b  = blockIdx.z;

    const size_t qrow0 = (size_t)b * SEQ + qt * 64;
    const size_t hoff  = (size_t)h * HDIM;

    auto fill = [&](int kb, int st) {
        const uint32_t base = sKV + st * ASTAGE_B;
#pragma unroll
        for (int l = 0; l < 4; l++) {
            const int idx = t + 128 * l;
            const int row = idx >> 3, ch = idx & 7;
            const uint32_t sw = SWZ((uint32_t)(row * 128 + ch * 16));
            const size_t g = ((size_t)b * SEQ + kb * 64 + row) * C3 + hoff + ch * 8;
            cpasync16(base + sw,           Gh + g + EMB);       // Kh
            cpasync16(base + KTILE_B + sw, Gh + g + 2 * EMB);   // Vh
        }
    };

    // prologue: Q tile + KV block 0 in one group
#pragma unroll
    for (int l = 0; l < 4; l++) {
        const int idx = t + 128 * l;
        const int row = idx >> 3, ch = idx & 7;
        const uint32_t sw = SWZ((uint32_t)(row * 128 + ch * 16));
        const size_t g = (qrow0 + row) * C3 + hoff + ch * 8;
        cpasync16(sQh + sw, Gh + g);
    }
    fill(0, 0);
    CP_COMMIT();
    CP_WAIT(0);
    __syncthreads();

    // Q fragments (registers, whole CTA lifetime)
    uint32_t qh[4][4];
#pragma unroll
    for (int ks = 0; ks < 4; ks++) {
        const int row = wid * 16 + a_mloc;
        const uint32_t sw = SWZ((uint32_t)(row * 128 + ks * 32 + a_kh * 16));
        ldsm4(qh[ks], sQh + sw);
    }

    float of[8][4];
#pragma unroll
    for (int i = 0; i < 8; i++)
#pragma unroll
        for (int e = 0; e < 4; e++) of[i][e] = 0.0f;
    float m_run[2] = {-1e30f, -1e30f};   // log2-domain running max
    float l_run[2] = {0.0f, 0.0f};

    const int nkb = qt + 1;
    for (int kb = 0; kb < nkb; kb++) {
        if (kb + 1 < nkb) {
            fill(kb + 1, (kb + 1) & 1);
            CP_COMMIT();
        }

        const uint32_t kbase = sKV + (kb & 1) * ASTAGE_B;

        // ---- S = Qh Kh^T (1 pass) ----
        float sf[8][4];
#pragma unroll
        for (int i = 0; i < 8; i++)
#pragma unroll
            for (int e = 0; e < 4; e++) sf[i][e] = 0.0f;

#pragma unroll
        for (int ks = 0; ks < 4; ks++) {
            uint32_t kh4[4][4];
#pragma unroll
            for (int g = 0; g < 4; g++) {
                const int row = g * 16 + b_nloc;
                const uint32_t sw = SWZ((uint32_t)(row * 128 + ks * 32 + b_kh * 16));
                ldsm4(kh4[g], kbase + sw);
            }
#pragma unroll
            for (int nt = 0; nt < 8; nt++)
                mma16816(sf[nt], qh[ks], kh4[nt >> 1][(nt & 1) * 2],
                         kh4[nt >> 1][(nt & 1) * 2 + 1]);
        }

        // ---- online softmax (log2 domain: p = 2^(s*SCALE_LOG2E - m)) ----
        const bool diag = (kb == qt);
#pragma unroll
        for (int half = 0; half < 2; half++) {
            const int rowg = qt * 64 + wid * 16 + (lane >> 2) + half * 8;
            float mx = -1e30f;
#pragma unroll
            for (int nt = 0; nt < 8; nt++)
#pragma unroll
                for (int e = 0; e < 2; e++) {
                    float v = sf[nt][half * 2 + e] * SCALE_LOG2E;
                    if (diag) {
                        const int colg = kb * 64 + nt * 8 + (lane & 3) * 2 + e;
                        if (colg > rowg) v = -1e30f;
                    }
                    sf[nt][half * 2 + e] = v;
                    mx = fmaxf(mx, v);
                }
            mx = fmaxf(mx, __shfl_xor_sync(0xffffffffu, mx, 1));
            mx = fmaxf(mx, __shfl_xor_sync(0xffffffffu, mx, 2));
            const float m_new = fmaxf(m_run[half], mx);
            const float corr  = ex2f(m_run[half] - m_new);
            float ls = 0.0f;
#pragma unroll
            for (int nt = 0; nt < 8; nt++)
#pragma unroll
                for (int e = 0; e < 2; e++) {
                    const float p = ex2f(sf[nt][half * 2 + e] - m_new);
                    sf[nt][half * 2 + e] = p;
                    ls += p;
                }
            l_run[half] = l_run[half] * corr + ls;   // lane-partial
            m_run[half] = m_new;
#pragma unroll
            for (int dt = 0; dt < 8; dt++) {
                of[dt][half * 2]     *= corr;
                of[dt][half * 2 + 1] *= corr;
            }
        }

        // ---- O += Ph Vh (1 pass) ----
        const uint32_t vbase = kbase + KTILE_B;
#pragma unroll
        for (int kc = 0; kc < 4; kc++) {
            uint32_t pa_h[4];
            pa_h[0] = pack_hi(sf[kc * 2][0],     sf[kc * 2][1]);
            pa_h[1] = pack_hi(sf[kc * 2][2],     sf[kc * 2][3]);
            pa_h[2] = pack_hi(sf[kc * 2 + 1][0], sf[kc * 2 + 1][1]);
            pa_h[3] = pack_hi(sf[kc * 2 + 1][2], sf[kc * 2 + 1][3]);

            uint32_t vh4[4][4];
#pragma unroll
            for (int dc = 0; dc < 4; dc++) {
                const int krow = kc * 16 + (lg & 1) * 8 + lr;
                const uint32_t sw =
                    SWZ((uint32_t)(krow * 128 + (dc * 16 + (lg >> 1) * 8) * 2));
                ldsm4t(vh4[dc], vbase + sw);
            }
#pragma unroll
            for (int dt = 0; dt < 8; dt++)
                mma16816(of[dt], pa_h, vh4[dt >> 1][(dt & 1) * 2],
                         vh4[dt >> 1][(dt & 1) * 2 + 1]);
        }

        if (kb + 1 < nkb) {
            CP_WAIT(0);
            __syncthreads();
        }
    }

    // ---- epilogue: y as fp16 ----
    float inv[2];
#pragma unroll
    for (int half = 0; half < 2; half++) {
        float l = l_run[half];
        l += __shfl_xor_sync(0xffffffffu, l, 1);
        l += __shfl_xor_sync(0xffffffffu, l, 2);
        inv[half] = 1.0f / l;
    }
    const size_t orow = qrow0 + wid * 16 + (lane >> 2);
    const size_t obase = orow * EMB + hoff + (lane & 3) * 2;
#pragma unroll
    for (int dt = 0; dt < 8; dt++) {
        *(uint32_t*)(Yh + obase + dt * 8) =
            pack_hi(of[dt][0] * inv[0], of[dt][1] * inv[0]);
        *(uint32_t*)(Yh + obase + 8 * EMB + dt * 8) =
            pack_hi(of[dt][2] * inv[1], of[dt][3] * inv[1]);
    }
}

// ---------------------------------------------------------------------------
// Launch
// ---------------------------------------------------------------------------
extern "C" void kernel_launch(void* const* d_in, const int* in_sizes, int n_in,
                              void* d_out, int out_size)
{
    const float* x      = (const float*)d_in[0];
    const float* w_attn = (const float*)d_in[1];
    const float* b_attn = (const float*)d_in[2];
    const float* w_proj = (const float*)d_in[3];
    const float* b_proj = (const float*)d_in[4];
    float* out = (float*)d_out;

    void* p;
    cudaGetSymbolAddress(&p, g_x_h);    __half* x_h   = (__half*)p;
    cudaGetSymbolAddress(&p, g_wa_h);   __half* wa_h  = (__half*)p;
    cudaGetSymbolAddress(&p, g_wp_h);   __half* wp_h  = (__half*)p;
    cudaGetSymbolAddress(&p, g_qkv_h);  __half* qkv_h = (__half*)p;
    cudaGetSymbolAddress(&p, g_y_h);    __half* y_h   = (__half*)p;

    cudaFuncSetAttribute(gemm_hmma<true>,
                         cudaFuncAttributeMaxDynamicSharedMemorySize, GSMEM);
    cudaFuncSetAttribute(gemm_hmma<false>,
                         cudaFuncAttributeMaxDynamicSharedMemorySize, GSMEM);
    cudaFuncSetAttribute(attn_hmma,
                         cudaFuncAttributeMaxDynamicSharedMemorySize, ASMEM);

    // 0) fp32 -> fp16 conversions
    {
        int n4 = MTOT * EMB / 4;
        split_kernel<<<n4 / 256, 256>>>((const float4*)x, (uint2*)x_h, n4);
        n4 = C3 * EMB / 4;
        split_kernel<<<n4 / 256, 256>>>((const float4*)w_attn, (uint2*)wa_h, n4);
        n4 = EMB * EMB / 4;
        split_kernel<<<n4 / 256, 256>>>((const float4*)w_proj, (uint2*)wp_h, n4);
    }

    // 1) qkv = x @ w_attn^T + b_attn (fp16 out)
    {
        dim3 grid(C3 / 64, MTOT / 128);
        gemm_hmma<true><<<grid, 128, GSMEM>>>(x_h, wa_h, b_attn,
                                              nullptr, qkv_h, MTOT, C3, EMB);
    }

    // 2) HMMA flash attention -> fp16 y
    {
        dim3 grid(SEQ / 64, HEADS, BATCH);
        attn_hmma<<<grid, 128, ASMEM>>>(qkv_h, y_h);
    }

    // 3) out = y @ w_proj^T + b_proj (fp32 out)
    {
        dim3 grid(EMB / 64, MTOT / 128);
        gemm_hmma<false><<<grid, 128, GSMEM>>>(y_h, wp_h, b_proj,
                                               out, nullptr, MTOT, EMB, EMB);
    }
}